// round 2
// baseline (speedup 1.0000x reference)
#include <cuda_runtime.h>

#define NN 50000
#define NE 600000
#define F  128

// ---------------- scratch (static device globals: no allocations) ----------
__device__ __align__(16) float g_W[F * F];          // combined W = W1^T W2^T, [k][n]
__device__ __align__(16) float g_c[F];              // combined bias
__device__ int   g_cnt[NN];                          // in-degree histogram (real edges)
__device__ int   g_rowstart[NN + 1];                 // CSR row offsets (by dst)
__device__ int   g_cursor[NN];                       // fill cursors
__device__ int   g_sorted[NE];                       // src indices sorted by dst
__device__ __align__(16) float g_agg[(size_t)NN * F];
__device__ __align__(16) float g_h[(size_t)NN * F];
__device__ int   d_is64;                             // 1 if edge_index is int64

// ---------------- dtype detection -------------------------------------------
// int64 little-endian with values < 2^31  =>  every odd 32-bit word is 0.
// int32 data: odd words are random edge indices; all-zero is impossible in practice.
__global__ void k_detect(const unsigned int* __restrict__ w) {
    __shared__ int nz;
    if (threadIdx.x == 0) nz = 0;
    __syncthreads();
    int local = 0;
    for (int i = threadIdx.x; i < 2048; i += blockDim.x)
        if (w[2 * i + 1] != 0u) local = 1;
    if (local) atomicOr(&nz, 1);
    __syncthreads();
    if (threadIdx.x == 0) d_is64 = (nz == 0) ? 1 : 0;
}

__device__ __forceinline__ int load_idx(const void* ei, int e, int row, int i) {
    if (d_is64) return (int)((const long long*)ei)[(size_t)row * e + i];
    return ((const int*)ei)[row * e + i];
}

// ---------------- param prep ----------------
// W[k][i] = sum_j w1[j][k] * w2[i][j]
__global__ void k_prep_w(const float* __restrict__ w1, const float* __restrict__ w2) {
    int k = blockIdx.x, i = threadIdx.x;
    float s = 0.f;
#pragma unroll 4
    for (int j = 0; j < F; j++) s += w1[j * F + k] * w2[i * F + j];
    g_W[k * F + i] = s;
}

// c[i] = sum_j b1[j] * w2[i][j] + b2[i]
__global__ void k_prep_c(const float* __restrict__ b1, const float* __restrict__ w2,
                         const float* __restrict__ b2) {
    int i = threadIdx.x;
    float s = b2[i];
#pragma unroll 4
    for (int j = 0; j < F; j++) s += b1[j] * w2[i * F + j];
    g_c[i] = s;
}

// ---------------- CSR build (counting sort by dst) ----------------
__global__ void k_zero_cnt(int n) {
    int i = blockIdx.x * blockDim.x + threadIdx.x;
    if (i < n) g_cnt[i] = 0;
}

__global__ void k_hist(const void* __restrict__ ei, int e, int n) {
    int i = blockIdx.x * blockDim.x + threadIdx.x;
    if (i < e) {
        int dst = load_idx(ei, e, 1, i);
        if ((unsigned)dst < (unsigned)n) atomicAdd(&g_cnt[dst], 1);
    }
}

// single-block exclusive scan of g_cnt -> g_rowstart, g_cursor
__global__ void k_scan(int n) {
    __shared__ int wsum[32];
    __shared__ int carry_s;
    int t = threadIdx.x;
    int lane = t & 31, w = t >> 5;
    if (t == 0) carry_s = 0;
    __syncthreads();
    for (int base = 0; base < n; base += 1024) {
        int v = (base + t < n) ? g_cnt[base + t] : 0;
        int x = v;
#pragma unroll
        for (int o = 1; o < 32; o <<= 1) {
            int y = __shfl_up_sync(0xFFFFFFFFu, x, o);
            if (lane >= o) x += y;
        }
        if (lane == 31) wsum[w] = x;
        __syncthreads();
        if (w == 0) {
            int s = wsum[lane];
#pragma unroll
            for (int o = 1; o < 32; o <<= 1) {
                int y = __shfl_up_sync(0xFFFFFFFFu, s, o);
                if (lane >= o) s += y;
            }
            wsum[lane] = s;
        }
        __syncthreads();
        int incl = x + (w > 0 ? wsum[w - 1] : 0);
        int excl = incl - v + carry_s;
        if (base + t < n) {
            g_rowstart[base + t] = excl;
            g_cursor[base + t]   = excl;
        }
        __syncthreads();
        if (t == 1023) carry_s += incl;   // incl of last thread == chunk total
        __syncthreads();
    }
    if (t == 0) g_rowstart[n] = carry_s;
}

__global__ void k_fill(const void* __restrict__ ei, int e, int n) {
    int i = blockIdx.x * blockDim.x + threadIdx.x;
    if (i < e) {
        int src = load_idx(ei, e, 0, i);
        int dst = load_idx(ei, e, 1, i);
        if ((unsigned)src < (unsigned)n && (unsigned)dst < (unsigned)n) {
            int p = atomicAdd(&g_cursor[dst], 1);
            g_sorted[p] = src;
        }
    }
}

// ---------------- aggregation: agg[n] = in[n] (self loop) + sum_{src->n} in[src]
// one warp per destination node, lane owns one float4 (16B) chunk of the row.
template <bool FROM_H>
__global__ void k_agg(const float* __restrict__ in_ext, int n) {
    int warp = (blockIdx.x * blockDim.x + threadIdx.x) >> 5;
    int lane = threadIdx.x & 31;
    if (warp >= n) return;
    const float4* hv = FROM_H ? (const float4*)g_h : (const float4*)in_ext;
    float4 acc = hv[(size_t)warp * 32 + lane];   // self loop
    int s  = g_rowstart[warp];
    int e2 = g_rowstart[warp + 1];
    for (int i = s; i < e2; i++) {
        int src = g_sorted[i];
        float4 v = hv[(size_t)src * 32 + lane];
        acc.x += v.x; acc.y += v.y; acc.z += v.z; acc.w += v.w;
    }
    ((float4*)g_agg)[(size_t)warp * 32 + lane] = acc;
}

// ---------------- GEMM: g_h[m][n] = sum_k g_agg[m][k] * g_W[k][n] + deg[m]*c[n]
#define BM 64
#define BN 128
#define BK 32
__global__ __launch_bounds__(128) void k_gemm(int M) {
    __shared__ float As[BM][BK + 1];   // +1 pad: conflict-free column reads
    __shared__ float Ws[BK][BN];
    int tid = threadIdx.x;
    int m0  = blockIdx.x * BM;
    int tx = tid & 15;   // n-group: 16 x 8 = 128
    int ty = tid >> 4;   // m-group:  8 x 8 = 64

    float acc[8][8];
#pragma unroll
    for (int j = 0; j < 8; j++)
#pragma unroll
        for (int i = 0; i < 8; i++) acc[j][i] = 0.f;

    for (int kc = 0; kc < F; kc += BK) {
        // load A tile 64x32 (512 float4 / 128 threads = 4 each)
#pragma unroll
        for (int i = 0; i < 4; i++) {
            int f   = tid + i * 128;
            int row = f >> 3;
            int c4  = (f & 7) * 4;
            float4 v = make_float4(0.f, 0.f, 0.f, 0.f);
            int gm = m0 + row;
            if (gm < M) v = *(const float4*)&g_agg[(size_t)gm * F + kc + c4];
            As[row][c4] = v.x; As[row][c4 + 1] = v.y;
            As[row][c4 + 2] = v.z; As[row][c4 + 3] = v.w;
        }
        // load W tile 32x128 (1024 float4 / 128 threads = 8 each)
#pragma unroll
        for (int i = 0; i < 8; i++) {
            int f   = tid + i * 128;
            int row = f >> 5;
            int c4  = (f & 31) * 4;
            *(float4*)&Ws[row][c4] = *(const float4*)&g_W[(size_t)(kc + row) * F + c4];
        }
        __syncthreads();
#pragma unroll
        for (int k = 0; k < BK; k++) {
            float a[8], b[8];
#pragma unroll
            for (int j = 0; j < 8; j++) a[j] = As[ty * 8 + j][k];
            float4 b0 = *(float4*)&Ws[k][tx * 8];
            float4 b1 = *(float4*)&Ws[k][tx * 8 + 4];
            b[0] = b0.x; b[1] = b0.y; b[2] = b0.z; b[3] = b0.w;
            b[4] = b1.x; b[5] = b1.y; b[6] = b1.z; b[7] = b1.w;
#pragma unroll
            for (int j = 0; j < 8; j++)
#pragma unroll
                for (int i = 0; i < 8; i++) acc[j][i] += a[j] * b[i];
        }
        __syncthreads();
    }

#pragma unroll
    for (int j = 0; j < 8; j++) {
        int gm = m0 + ty * 8 + j;
        if (gm < M) {
            float deg = (float)(g_cnt[gm] + 1);
#pragma unroll
            for (int i = 0; i < 8; i += 4) {
                int nn = tx * 8 + i;
                float4 o;
                o.x = acc[j][i]     + deg * g_c[nn];
                o.y = acc[j][i + 1] + deg * g_c[nn + 1];
                o.z = acc[j][i + 2] + deg * g_c[nn + 2];
                o.w = acc[j][i + 3] + deg * g_c[nn + 3];
                *(float4*)&g_h[(size_t)gm * F + nn] = o;
            }
        }
    }
}

// ---------------- row-wise log_softmax: one warp per row ----------------
__global__ void k_logsoftmax(float* __restrict__ out, int n) {
    int warp = (blockIdx.x * blockDim.x + threadIdx.x) >> 5;
    int lane = threadIdx.x & 31;
    if (warp >= n) return;
    float4 v = *(const float4*)&g_h[(size_t)warp * F + lane * 4];
    float mx = fmaxf(fmaxf(v.x, v.y), fmaxf(v.z, v.w));
#pragma unroll
    for (int o = 16; o; o >>= 1) mx = fmaxf(mx, __shfl_xor_sync(0xFFFFFFFFu, mx, o));
    float s = expf(v.x - mx) + expf(v.y - mx) + expf(v.z - mx) + expf(v.w - mx);
#pragma unroll
    for (int o = 16; o; o >>= 1) s += __shfl_xor_sync(0xFFFFFFFFu, s, o);
    float l = mx + logf(s);
    float4 o4;
    o4.x = v.x - l; o4.y = v.y - l; o4.z = v.z - l; o4.w = v.w - l;
    *(float4*)&out[(size_t)warp * F + lane * 4] = o4;
}

// ---------------- launch ----------------
extern "C" void kernel_launch(void* const* d_in, const int* in_sizes, int n_in,
                              void* d_out, int out_size) {
    const float* x  = (const float*)d_in[0];
    const void*  ei = d_in[1];
    const float* w1 = (const float*)d_in[2];
    const float* b1 = (const float*)d_in[3];
    const float* w2 = (const float*)d_in[4];
    const float* b2 = (const float*)d_in[5];
    float* out = (float*)d_out;

    int n = in_sizes[0] / F;     // 50000
    int e = in_sizes[1] / 2;     // 600000

    // detect int32 vs int64 edge_index
    k_detect<<<1, 1024>>>((const unsigned int*)ei);

    // fold the two linear layers: W = W1^T W2^T, c = b1 W2^T + b2
    k_prep_w<<<F, F>>>(w1, w2);
    k_prep_c<<<1, F>>>(b1, w2, b2);

    // CSR by dst (counting sort) — shared by both convs
    k_zero_cnt<<<(n + 255) / 256, 256>>>(n);
    k_hist<<<(e + 255) / 256, 256>>>(ei, e, n);
    k_scan<<<1, 1024>>>(n);
    k_fill<<<(e + 255) / 256, 256>>>(ei, e, n);

    int agg_blocks  = (n * 32 + 255) / 256;
    int gemm_blocks = (n + BM - 1) / BM;

    // conv1: agg = x + A x ; h = agg W + deg*c
    k_agg<false><<<agg_blocks, 256>>>(x, n);
    k_gemm<<<gemm_blocks, 128>>>(n);
    // conv2: agg = h + A h ; h = agg W + deg*c
    k_agg<true><<<agg_blocks, 256>>>(nullptr, n);
    k_gemm<<<gemm_blocks, 128>>>(n);

    // log_softmax rows -> d_out
    k_logsoftmax<<<agg_blocks, 256>>>(out, n);
}

// round 6
// speedup vs baseline: 1.3189x; 1.3189x over previous
#include <cuda_runtime.h>
#include <stdint.h>

#define NN 50000
#define NE 600000
#define F  128
#define GBM 64

// ---------------- scratch (static device globals: no allocations) ----------
__device__ __align__(16) float    g_W[F * F];            // combined W = W1^T W2^T, [k][n]
__device__ __align__(16) uint32_t g_Wf[16 * 16 * 32 * 2];// W in mma B-fragment order (tf32)
__device__ __align__(16) float    g_c[F];                // combined bias
__device__ int   g_cnt[NN];                              // in-degree histogram (real edges)
__device__ int   g_rowstart[NN + 1];                     // CSR row offsets (by dst)
__device__ int   g_cursor[NN];                           // fill cursors
__device__ int   g_sorted[NE];                           // src indices sorted by dst
__device__ __align__(16) float g_h[(size_t)NN * F];      // intermediate h1
__device__ int   d_is64;                                 // 1 if edge_index is int64

__device__ __forceinline__ uint32_t f2tf(float f) {
    uint32_t u;
    asm("cvt.rna.tf32.f32 %0, %1;" : "=r"(u) : "f"(f));
    return u;
}

// ---------------- dtype detection (int32 vs int64 edge_index) ---------------
__global__ void k_detect(const unsigned int* __restrict__ w) {
    __shared__ int nz;
    if (threadIdx.x == 0) nz = 0;
    __syncthreads();
    int local = 0;
    for (int i = threadIdx.x; i < 2048; i += blockDim.x)
        if (w[2 * i + 1] != 0u) local = 1;
    if (local) atomicOr(&nz, 1);
    __syncthreads();
    if (threadIdx.x == 0) d_is64 = (nz == 0) ? 1 : 0;
}

__device__ __forceinline__ int load_idx(const void* ei, int e, int row, int i) {
    if (d_is64) return (int)((const long long*)ei)[(size_t)row * e + i];
    return ((const int*)ei)[row * e + i];
}

// ---------------- param prep ----------------
__global__ void k_prep_w(const float* __restrict__ w1, const float* __restrict__ w2) {
    int k = blockIdx.x, i = threadIdx.x;
    float s = 0.f;
#pragma unroll 4
    for (int j = 0; j < F; j++) s += w1[j * F + k] * w2[i * F + j];
    g_W[k * F + i] = s;
}

__global__ void k_prep_c(const float* __restrict__ b1, const float* __restrict__ w2,
                         const float* __restrict__ b2) {
    int i = threadIdx.x;
    float s = b2[i];
#pragma unroll 4
    for (int j = 0; j < F; j++) s += b1[j] * w2[i * F + j];
    g_c[i] = s;
}

// repack W into mma B-fragment order: [kc][nt][lane] -> (b0,b1), tf32 bits.
__global__ void k_prep_wf() {
    int idx = blockIdx.x * blockDim.x + threadIdx.x;  // 0 .. 8191
    if (idx >= 16 * 16 * 32) return;
    int lane = idx & 31;
    int nt   = (idx >> 5) & 15;
    int kc   = idx >> 9;
    int tig = lane & 3, gid = lane >> 2;
    int k0 = kc * 8 + tig, n = nt * 8 + gid;
    g_Wf[idx * 2 + 0] = f2tf(g_W[k0 * F + n]);
    g_Wf[idx * 2 + 1] = f2tf(g_W[(k0 + 4) * F + n]);
}

// ---------------- CSR build (counting sort by dst) ----------------
__global__ void k_zero_cnt(int n) {
    int i = blockIdx.x * blockDim.x + threadIdx.x;
    if (i < n) g_cnt[i] = 0;
}

__global__ void k_hist(const void* __restrict__ ei, int e, int n) {
    int i = blockIdx.x * blockDim.x + threadIdx.x;
    if (i < e) {
        int dst = load_idx(ei, e, 1, i);
        if ((unsigned)dst < (unsigned)n) atomicAdd(&g_cnt[dst], 1);
    }
}

__global__ void k_scan(int n) {
    __shared__ int wsum[32];
    __shared__ int carry_s;
    int t = threadIdx.x;
    int lane = t & 31, w = t >> 5;
    if (t == 0) carry_s = 0;
    __syncthreads();
    for (int base = 0; base < n; base += 1024) {
        int v = (base + t < n) ? g_cnt[base + t] : 0;
        int x = v;
#pragma unroll
        for (int o = 1; o < 32; o <<= 1) {
            int y = __shfl_up_sync(0xFFFFFFFFu, x, o);
            if (lane >= o) x += y;
        }
        if (lane == 31) wsum[w] = x;
        __syncthreads();
        if (w == 0) {
            int s = wsum[lane];
#pragma unroll
            for (int o = 1; o < 32; o <<= 1) {
                int y = __shfl_up_sync(0xFFFFFFFFu, s, o);
                if (lane >= o) s += y;
            }
            wsum[lane] = s;
        }
        __syncthreads();
        int incl = x + (w > 0 ? wsum[w - 1] : 0);
        int excl = incl - v + carry_s;
        if (base + t < n) {
            g_rowstart[base + t] = excl;
            g_cursor[base + t]   = excl;
        }
        __syncthreads();
        if (t == 1023) carry_s += incl;
        __syncthreads();
    }
    if (t == 0) g_rowstart[n] = carry_s;
}

__global__ void k_fill(const void* __restrict__ ei, int e, int n) {
    int i = blockIdx.x * blockDim.x + threadIdx.x;
    if (i < e) {
        int src = load_idx(ei, e, 0, i);
        int dst = load_idx(ei, e, 1, i);
        if ((unsigned)src < (unsigned)n && (unsigned)dst < (unsigned)n) {
            int p = atomicAdd(&g_cursor[dst], 1);
            g_sorted[p] = src;
        }
    }
}

// ---------------- fused conv: gather-agg + TF32 MMA + epilogue --------------
// 512 threads / 16 warps. Warp w: m-quadrant (w&3)*16 rows, n-quadrant (w>>2)*32 cols.
// FIRST=true : src = x (param),        dst = g_h (device symbol, referenced on device)
// FIRST=false: src = g_h (dev symbol), dst = out (param)
// NOTE: __device__ symbols are never passed as host-side kernel arguments.
#define MMA_TF32(c0, c1, c2, c3, bx, by)                                      \
    asm volatile(                                                             \
        "mma.sync.aligned.m16n8k8.row.col.f32.tf32.tf32.f32 "                 \
        "{%0,%1,%2,%3}, {%4,%5,%6,%7}, {%8,%9}, {%0,%1,%2,%3};"               \
        : "+f"(c0), "+f"(c1), "+f"(c2), "+f"(c3)                              \
        : "r"(a0), "r"(a1), "r"(a2), "r"(a3), "r"(bx), "r"(by))

template <bool FIRST>
__global__ __launch_bounds__(512) void k_conv(const float* __restrict__ src_param,
                                              float* __restrict__ dst_param, int M) {
    __shared__ uint32_t As[GBM * 132];   // 64 rows, pitch 132 words (bank = lane)
    int tid = threadIdx.x;
    int warp = tid >> 5, lane = tid & 31;
    int gid = lane >> 2, tig = lane & 3;
    int m0 = blockIdx.x * GBM;

    const float4* hv = FIRST ? (const float4*)src_param : (const float4*)g_h;
    float*        dp = FIRST ? g_h : dst_param;

    // ---- aggregation: warp handles rows [warp*4, warp*4+4), lane = 16B chunk
#pragma unroll
    for (int r = 0; r < 4; r++) {
        int row = warp * 4 + r;
        int gm  = m0 + row;
        float4 a = make_float4(0.f, 0.f, 0.f, 0.f);
        if (gm < M) {
            a = hv[(size_t)gm * 32 + lane];           // self loop
            int s = g_rowstart[gm], e2 = g_rowstart[gm + 1];
            int i = s;
            for (; i + 1 < e2; i += 2) {              // MLP=2
                int s0 = g_sorted[i], s1 = g_sorted[i + 1];
                float4 v0 = hv[(size_t)s0 * 32 + lane];
                float4 v1 = hv[(size_t)s1 * 32 + lane];
                a.x += v0.x + v1.x; a.y += v0.y + v1.y;
                a.z += v0.z + v1.z; a.w += v0.w + v1.w;
            }
            if (i < e2) {
                float4 v = hv[(size_t)g_sorted[i] * 32 + lane];
                a.x += v.x; a.y += v.y; a.z += v.z; a.w += v.w;
            }
        }
        uint4 t;
        t.x = f2tf(a.x); t.y = f2tf(a.y); t.z = f2tf(a.z); t.w = f2tf(a.w);
        *(uint4*)&As[row * 132 + lane * 4] = t;
    }
    __syncthreads();

    // ---- TF32 mma: quadrant (mrow0, 4 n-tiles starting at nt0)
    int mrow0 = (warp & 3) * 16;
    int nt0   = (warp >> 2) * 4;

    float c00 = 0.f, c01 = 0.f, c02 = 0.f, c03 = 0.f;
    float c10 = 0.f, c11 = 0.f, c12 = 0.f, c13 = 0.f;
    float c20 = 0.f, c21 = 0.f, c22 = 0.f, c23 = 0.f;
    float c30 = 0.f, c31 = 0.f, c32 = 0.f, c33 = 0.f;

    int abase = (mrow0 + gid) * 132;
    for (int kc = 0; kc < 16; kc++) {
        uint32_t a0 = As[abase + kc * 8 + tig];
        uint32_t a1 = As[abase + 8 * 132 + kc * 8 + tig];
        uint32_t a2 = As[abase + kc * 8 + tig + 4];
        uint32_t a3 = As[abase + 8 * 132 + kc * 8 + tig + 4];
        const uint2* wf = (const uint2*)g_Wf + (size_t)kc * 512 + nt0 * 32 + lane;
        uint2 b0 = wf[0];
        uint2 b1 = wf[32];
        uint2 b2 = wf[64];
        uint2 b3 = wf[96];
        MMA_TF32(c00, c01, c02, c03, b0.x, b0.y);
        MMA_TF32(c10, c11, c12, c13, b1.x, b1.y);
        MMA_TF32(c20, c21, c22, c23, b2.x, b2.y);
        MMA_TF32(c30, c31, c32, c33, b3.x, b3.y);
    }

    // ---- epilogue: + deg*c, store (c0,c1 -> row r0; c2,c3 -> row r1)
    int r0 = m0 + mrow0 + gid;
    int r1 = r0 + 8;
    float deg0 = (r0 < M) ? (float)(g_cnt[r0] + 1) : 0.f;
    float deg1 = (r1 < M) ? (float)(g_cnt[r1] + 1) : 0.f;
    int n0 = nt0 * 8 + 2 * tig;

    float w0 = g_c[n0],      w1 = g_c[n0 + 1];
    float w2 = g_c[n0 + 8],  w3 = g_c[n0 + 9];
    float w4 = g_c[n0 + 16], w5 = g_c[n0 + 17];
    float w6 = g_c[n0 + 24], w7 = g_c[n0 + 25];

    if (r0 < M) {
        *(float2*)&dp[(size_t)r0 * F + n0]      = make_float2(c00 + deg0 * w0, c01 + deg0 * w1);
        *(float2*)&dp[(size_t)r0 * F + n0 + 8]  = make_float2(c10 + deg0 * w2, c11 + deg0 * w3);
        *(float2*)&dp[(size_t)r0 * F + n0 + 16] = make_float2(c20 + deg0 * w4, c21 + deg0 * w5);
        *(float2*)&dp[(size_t)r0 * F + n0 + 24] = make_float2(c30 + deg0 * w6, c31 + deg0 * w7);
    }
    if (r1 < M) {
        *(float2*)&dp[(size_t)r1 * F + n0]      = make_float2(c02 + deg1 * w0, c03 + deg1 * w1);
        *(float2*)&dp[(size_t)r1 * F + n0 + 8]  = make_float2(c12 + deg1 * w2, c13 + deg1 * w3);
        *(float2*)&dp[(size_t)r1 * F + n0 + 16] = make_float2(c22 + deg1 * w4, c23 + deg1 * w5);
        *(float2*)&dp[(size_t)r1 * F + n0 + 24] = make_float2(c32 + deg1 * w6, c33 + deg1 * w7);
    }
}

// ---------------- row-wise log_softmax, in place: one warp per row ----------
__global__ void k_logsoftmax(float* __restrict__ io, int n) {
    int warp = (blockIdx.x * blockDim.x + threadIdx.x) >> 5;
    int lane = threadIdx.x & 31;
    if (warp >= n) return;
    float4 v = *(const float4*)&io[(size_t)warp * F + lane * 4];
    float mx = fmaxf(fmaxf(v.x, v.y), fmaxf(v.z, v.w));
#pragma unroll
    for (int o = 16; o; o >>= 1) mx = fmaxf(mx, __shfl_xor_sync(0xFFFFFFFFu, mx, o));
    float s = expf(v.x - mx) + expf(v.y - mx) + expf(v.z - mx) + expf(v.w - mx);
#pragma unroll
    for (int o = 16; o; o >>= 1) s += __shfl_xor_sync(0xFFFFFFFFu, s, o);
    float l = mx + logf(s);
    float4 o4;
    o4.x = v.x - l; o4.y = v.y - l; o4.z = v.z - l; o4.w = v.w - l;
    *(float4*)&io[(size_t)warp * F + lane * 4] = o4;
}

// ---------------- launch ----------------
extern "C" void kernel_launch(void* const* d_in, const int* in_sizes, int n_in,
                              void* d_out, int out_size) {
    const float* x  = (const float*)d_in[0];
    const void*  ei = d_in[1];
    const float* w1 = (const float*)d_in[2];
    const float* b1 = (const float*)d_in[3];
    const float* w2 = (const float*)d_in[4];
    const float* b2 = (const float*)d_in[5];
    float* out = (float*)d_out;

    int n = in_sizes[0] / F;     // 50000
    int e = in_sizes[1] / 2;     // 600000

    k_detect<<<1, 1024>>>((const unsigned int*)ei);

    // fold the two linear layers: W = W1^T W2^T, c = b1 W2^T + b2; pack fragments
    k_prep_w<<<F, F>>>(w1, w2);
    k_prep_c<<<1, F>>>(b1, w2, b2);
    k_prep_wf<<<32, 256>>>();

    // CSR by dst (counting sort) — shared by both convs
    k_zero_cnt<<<(n + 255) / 256, 256>>>(n);
    k_hist<<<(e + 255) / 256, 256>>>(ei, e, n);
    k_scan<<<1, 1024>>>(n);
    k_fill<<<(e + 255) / 256, 256>>>(ei, e, n);

    int conv_blocks = (n + GBM - 1) / GBM;

    // conv1: g_h = conv(x)   conv2: out = conv(g_h)   then log_softmax in place
    k_conv<true><<<conv_blocks, 512>>>(x, nullptr, n);
    k_conv<false><<<conv_blocks, 512>>>(nullptr, out, n);
    k_logsoftmax<<<(n * 32 + 255) / 256, 256>>>(out, n);
}

// round 7
// speedup vs baseline: 1.6216x; 1.2295x over previous
#include <cuda_runtime.h>
#include <stdint.h>

#define NN 50000
#define NE 600000
#define F  128
#define GBM 64

// ---------------- scratch (static device globals: no allocations) ----------
__device__ __align__(16) float    g_W[F * F];            // combined W = W1^T W2^T, [k][n]
__device__ __align__(16) uint32_t g_Wf[16 * 16 * 32 * 2];// W in mma B-fragment order (tf32)
__device__ __align__(16) float    g_c[F];                // combined bias
__device__ int   g_cnt[NN];                              // in-degree histogram (real edges)
__device__ int   g_rowstart[NN + 1];                     // CSR row offsets (by dst)
__device__ int   g_cursor[NN];                           // fill cursors
__device__ int   g_bsum[128];                            // per-block scan sums
__device__ int   g_sorted[NE];                           // src indices sorted by dst
__device__ __align__(16) float g_h[(size_t)NN * F];      // intermediate h1
__device__ int   d_is64;                                 // 1 if edge_index is int64

__device__ __forceinline__ uint32_t f2tf(float f) {
    uint32_t u;
    asm("cvt.rna.tf32.f32 %0, %1;" : "=r"(u) : "f"(f));
    return u;
}

// ---------------- dtype detection (int32 vs int64 edge_index) ---------------
__global__ void k_detect(const unsigned int* __restrict__ w) {
    __shared__ int nz;
    if (threadIdx.x == 0) nz = 0;
    __syncthreads();
    int local = 0;
    for (int i = threadIdx.x; i < 2048; i += blockDim.x)
        if (w[2 * i + 1] != 0u) local = 1;
    if (local) atomicOr(&nz, 1);
    __syncthreads();
    if (threadIdx.x == 0) d_is64 = (nz == 0) ? 1 : 0;
}

__device__ __forceinline__ int load_idx(const void* ei, int e, int row, int i) {
    if (d_is64) return (int)((const long long*)ei)[(size_t)row * e + i];
    return ((const int*)ei)[row * e + i];
}

// ---------------- param prep (W fold + bias fold merged) --------------------
__global__ void k_prep_wc(const float* __restrict__ w1, const float* __restrict__ w2,
                          const float* __restrict__ b1, const float* __restrict__ b2) {
    int i = threadIdx.x;
    if (blockIdx.x == F) {                      // bias block
        float s = b2[i];
#pragma unroll 4
        for (int j = 0; j < F; j++) s += b1[j] * w2[i * F + j];
        g_c[i] = s;
        return;
    }
    int k = blockIdx.x;
    float s = 0.f;
#pragma unroll 4
    for (int j = 0; j < F; j++) s += w1[j * F + k] * w2[i * F + j];
    g_W[k * F + i] = s;
}

// repack W into mma B-fragment order: [kc][nt][lane] -> (b0,b1), tf32 bits.
__global__ void k_prep_wf() {
    int idx = blockIdx.x * blockDim.x + threadIdx.x;  // 0 .. 8191
    if (idx >= 16 * 16 * 32) return;
    int lane = idx & 31;
    int nt   = (idx >> 5) & 15;
    int kc   = idx >> 9;
    int tig = lane & 3, gid = lane >> 2;
    int k0 = kc * 8 + tig, n = nt * 8 + gid;
    g_Wf[idx * 2 + 0] = f2tf(g_W[k0 * F + n]);
    g_Wf[idx * 2 + 1] = f2tf(g_W[(k0 + 4) * F + n]);
}

// ---------------- CSR build (counting sort by dst) ----------------
__global__ void k_zero_cnt(int n) {
    int i = blockIdx.x * blockDim.x + threadIdx.x;
    if (i < n) g_cnt[i] = 0;
}

__global__ void k_hist(const void* __restrict__ ei, int e, int n) {
    int i = blockIdx.x * blockDim.x + threadIdx.x;
    if (i < e) {
        int dst = load_idx(ei, e, 1, i);
        if ((unsigned)dst < (unsigned)n) atomicAdd(&g_cnt[dst], 1);
    }
}

// phase 1: per-block (512) exclusive scan -> g_rowstart (local), total -> g_bsum
__global__ __launch_bounds__(512) void k_scan_block(int n) {
    __shared__ int wsum[16];
    int t = threadIdx.x, lane = t & 31, w = t >> 5;
    int gidx = blockIdx.x * 512 + t;
    int v = (gidx < n) ? g_cnt[gidx] : 0;
    int x = v;
#pragma unroll
    for (int o = 1; o < 32; o <<= 1) {
        int y = __shfl_up_sync(0xFFFFFFFFu, x, o);
        if (lane >= o) x += y;
    }
    if (lane == 31) wsum[w] = x;
    __syncthreads();
    if (w == 0 && lane < 16) {
        int s = wsum[lane];
#pragma unroll
        for (int o = 1; o < 16; o <<= 1) {
            int y = __shfl_up_sync(0xFFFFu, s, o);
            if (lane >= o) s += y;
        }
        wsum[lane] = s;
    }
    __syncthreads();
    int incl = x + (w > 0 ? wsum[w - 1] : 0);
    if (gidx < n) g_rowstart[gidx] = incl - v;
    if (t == 511) g_bsum[blockIdx.x] = incl;
}

// phase 2: one warp scans the (<=128) block sums; writes g_rowstart[n] = total
__global__ void k_scan_top(int nb, int n) {
    int lane = threadIdx.x;
    int carry = 0;
    for (int base = 0; base < nb; base += 32) {
        int v = (base + lane < nb) ? g_bsum[base + lane] : 0;
        int x = v;
#pragma unroll
        for (int o = 1; o < 32; o <<= 1) {
            int y = __shfl_up_sync(0xFFFFFFFFu, x, o);
            if (lane >= o) x += y;
        }
        if (base + lane < nb) g_bsum[base + lane] = x - v + carry;
        carry += __shfl_sync(0xFFFFFFFFu, x, 31);
    }
    if (lane == 0) g_rowstart[n] = carry;
}

// phase 3: add block offsets; init cursors
__global__ __launch_bounds__(512) void k_scan_add(int n) {
    int gidx = blockIdx.x * 512 + threadIdx.x;
    if (gidx < n) {
        int v = g_rowstart[gidx] + g_bsum[blockIdx.x];
        g_rowstart[gidx] = v;
        g_cursor[gidx]   = v;
    }
}

__global__ void k_fill(const void* __restrict__ ei, int e, int n) {
    int i = blockIdx.x * blockDim.x + threadIdx.x;
    if (i < e) {
        int src = load_idx(ei, e, 0, i);
        int dst = load_idx(ei, e, 1, i);
        if ((unsigned)src < (unsigned)n && (unsigned)dst < (unsigned)n) {
            int p = atomicAdd(&g_cursor[dst], 1);
            g_sorted[p] = src;
        }
    }
}

// ---------------- fused conv: gather-agg + TF32 MMA + epilogue --------------
// 512 threads / 16 warps. Warp w: m-quadrant (w&3)*16 rows, n-quadrant (w>>2)*32 cols.
// FIRST : src = x (param),  dst = g_h.    else: src = g_h, dst = out (param).
// LSM   : apply row-wise log_softmax in the epilogue (cross-warp via smem).
#define MMA_TF32(c0, c1, c2, c3, bx, by)                                      \
    asm volatile(                                                             \
        "mma.sync.aligned.m16n8k8.row.col.f32.tf32.tf32.f32 "                 \
        "{%0,%1,%2,%3}, {%4,%5,%6,%7}, {%8,%9}, {%0,%1,%2,%3};"               \
        : "+f"(c0), "+f"(c1), "+f"(c2), "+f"(c3)                              \
        : "r"(a0), "r"(a1), "r"(a2), "r"(a3), "r"(bx), "r"(by))

template <bool FIRST, bool LSM>
__global__ __launch_bounds__(512) void k_conv(const float* __restrict__ src_param,
                                              float* __restrict__ dst_param, int M) {
    __shared__ uint32_t As[GBM * 132];   // 64 rows, pitch 132 words (bank = lane)
    __shared__ float sredm[GBM][4];      // per-row per-nquad max
    __shared__ float sreds[GBM][4];      // per-row per-nquad expsum
    int tid = threadIdx.x;
    int warp = tid >> 5, lane = tid & 31;
    int gid = lane >> 2, tig = lane & 3;
    int m0 = blockIdx.x * GBM;

    const float4* hv = FIRST ? (const float4*)src_param : (const float4*)g_h;
    float*        dp = FIRST ? g_h : dst_param;

    // ---- aggregation: warp handles rows [warp*4, warp*4+4), lane = 16B chunk
#pragma unroll
    for (int r = 0; r < 4; r++) {
        int row = warp * 4 + r;
        int gm  = m0 + row;
        float4 a = make_float4(0.f, 0.f, 0.f, 0.f);
        if (gm < M) {
            a = hv[(size_t)gm * 32 + lane];           // self loop
            int s = g_rowstart[gm], e2 = g_rowstart[gm + 1];
            int i = s;
            for (; i + 3 < e2; i += 4) {              // MLP=4
                int s0 = g_sorted[i],     s1 = g_sorted[i + 1];
                int s2 = g_sorted[i + 2], s3 = g_sorted[i + 3];
                float4 v0 = hv[(size_t)s0 * 32 + lane];
                float4 v1 = hv[(size_t)s1 * 32 + lane];
                float4 v2 = hv[(size_t)s2 * 32 + lane];
                float4 v3 = hv[(size_t)s3 * 32 + lane];
                a.x += (v0.x + v1.x) + (v2.x + v3.x);
                a.y += (v0.y + v1.y) + (v2.y + v3.y);
                a.z += (v0.z + v1.z) + (v2.z + v3.z);
                a.w += (v0.w + v1.w) + (v2.w + v3.w);
            }
            for (; i < e2; i++) {
                float4 v = hv[(size_t)g_sorted[i] * 32 + lane];
                a.x += v.x; a.y += v.y; a.z += v.z; a.w += v.w;
            }
        }
        uint4 t;
        t.x = f2tf(a.x); t.y = f2tf(a.y); t.z = f2tf(a.z); t.w = f2tf(a.w);
        *(uint4*)&As[row * 132 + lane * 4] = t;
    }
    __syncthreads();

    // ---- TF32 mma: quadrant (mrow0, 4 n-tiles starting at nt0)
    int mrow0 = (warp & 3) * 16;
    int nq    = warp >> 2;          // n-quadrant 0..3
    int nt0   = nq * 4;

    float c00 = 0.f, c01 = 0.f, c02 = 0.f, c03 = 0.f;
    float c10 = 0.f, c11 = 0.f, c12 = 0.f, c13 = 0.f;
    float c20 = 0.f, c21 = 0.f, c22 = 0.f, c23 = 0.f;
    float c30 = 0.f, c31 = 0.f, c32 = 0.f, c33 = 0.f;

    int abase = (mrow0 + gid) * 132;
    for (int kc = 0; kc < 16; kc++) {
        uint32_t a0 = As[abase + kc * 8 + tig];
        uint32_t a1 = As[abase + 8 * 132 + kc * 8 + tig];
        uint32_t a2 = As[abase + kc * 8 + tig + 4];
        uint32_t a3 = As[abase + 8 * 132 + kc * 8 + tig + 4];
        const uint2* wf = (const uint2*)g_Wf + (size_t)kc * 512 + nt0 * 32 + lane;
        uint2 b0 = wf[0];
        uint2 b1 = wf[32];
        uint2 b2 = wf[64];
        uint2 b3 = wf[96];
        MMA_TF32(c00, c01, c02, c03, b0.x, b0.y);
        MMA_TF32(c10, c11, c12, c13, b1.x, b1.y);
        MMA_TF32(c20, c21, c22, c23, b2.x, b2.y);
        MMA_TF32(c30, c31, c32, c33, b3.x, b3.y);
    }

    // ---- epilogue: bias (deg*c)
    int row0 = mrow0 + gid;          // in-block row of c0x,c1x,c2x,c3x (x=0,1)
    int row1 = row0 + 8;             // in-block row of c?2,c?3
    int r0 = m0 + row0;
    int r1 = m0 + row1;
    float deg0 = (r0 < M) ? (float)(g_cnt[r0] + 1) : 0.f;
    float deg1 = (r1 < M) ? (float)(g_cnt[r1] + 1) : 0.f;
    int n0 = nt0 * 8 + 2 * tig;

    float w0 = g_c[n0],      w1 = g_c[n0 + 1];
    float w2 = g_c[n0 + 8],  w3 = g_c[n0 + 9];
    float w4 = g_c[n0 + 16], w5 = g_c[n0 + 17];
    float w6 = g_c[n0 + 24], w7 = g_c[n0 + 25];

    c00 += deg0 * w0; c01 += deg0 * w1; c10 += deg0 * w2; c11 += deg0 * w3;
    c20 += deg0 * w4; c21 += deg0 * w5; c30 += deg0 * w6; c31 += deg0 * w7;
    c02 += deg1 * w0; c03 += deg1 * w1; c12 += deg1 * w2; c13 += deg1 * w3;
    c22 += deg1 * w4; c23 += deg1 * w5; c32 += deg1 * w6; c33 += deg1 * w7;

    if (LSM) {
        // per-thread max over this warp's 8 cols of each row, reduce tig group
        float m0v = fmaxf(fmaxf(fmaxf(c00, c01), fmaxf(c10, c11)),
                          fmaxf(fmaxf(c20, c21), fmaxf(c30, c31)));
        float m1v = fmaxf(fmaxf(fmaxf(c02, c03), fmaxf(c12, c13)),
                          fmaxf(fmaxf(c22, c23), fmaxf(c32, c33)));
        m0v = fmaxf(m0v, __shfl_xor_sync(0xFFFFFFFFu, m0v, 1));
        m0v = fmaxf(m0v, __shfl_xor_sync(0xFFFFFFFFu, m0v, 2));
        m1v = fmaxf(m1v, __shfl_xor_sync(0xFFFFFFFFu, m1v, 1));
        m1v = fmaxf(m1v, __shfl_xor_sync(0xFFFFFFFFu, m1v, 2));
        if (tig == 0) { sredm[row0][nq] = m0v; sredm[row1][nq] = m1v; }
        __syncthreads();
        float rm0 = fmaxf(fmaxf(sredm[row0][0], sredm[row0][1]),
                          fmaxf(sredm[row0][2], sredm[row0][3]));
        float rm1 = fmaxf(fmaxf(sredm[row1][0], sredm[row1][1]),
                          fmaxf(sredm[row1][2], sredm[row1][3]));
        float s0 = __expf(c00 - rm0) + __expf(c01 - rm0) + __expf(c10 - rm0) +
                   __expf(c11 - rm0) + __expf(c20 - rm0) + __expf(c21 - rm0) +
                   __expf(c30 - rm0) + __expf(c31 - rm0);
        float s1 = __expf(c02 - rm1) + __expf(c03 - rm1) + __expf(c12 - rm1) +
                   __expf(c13 - rm1) + __expf(c22 - rm1) + __expf(c23 - rm1) +
                   __expf(c32 - rm1) + __expf(c33 - rm1);
        s0 += __shfl_xor_sync(0xFFFFFFFFu, s0, 1);
        s0 += __shfl_xor_sync(0xFFFFFFFFu, s0, 2);
        s1 += __shfl_xor_sync(0xFFFFFFFFu, s1, 1);
        s1 += __shfl_xor_sync(0xFFFFFFFFu, s1, 2);
        if (tig == 0) { sreds[row0][nq] = s0; sreds[row1][nq] = s1; }
        __syncthreads();
        float t0 = (sreds[row0][0] + sreds[row0][1]) + (sreds[row0][2] + sreds[row0][3]);
        float t1 = (sreds[row1][0] + sreds[row1][1]) + (sreds[row1][2] + sreds[row1][3]);
        float l0 = rm0 + __logf(t0);
        float l1 = rm1 + __logf(t1);
        c00 -= l0; c01 -= l0; c10 -= l0; c11 -= l0;
        c20 -= l0; c21 -= l0; c30 -= l0; c31 -= l0;
        c02 -= l1; c03 -= l1; c12 -= l1; c13 -= l1;
        c22 -= l1; c23 -= l1; c32 -= l1; c33 -= l1;
    }

    if (r0 < M) {
        *(float2*)&dp[(size_t)r0 * F + n0]      = make_float2(c00, c01);
        *(float2*)&dp[(size_t)r0 * F + n0 + 8]  = make_float2(c10, c11);
        *(float2*)&dp[(size_t)r0 * F + n0 + 16] = make_float2(c20, c21);
        *(float2*)&dp[(size_t)r0 * F + n0 + 24] = make_float2(c30, c31);
    }
    if (r1 < M) {
        *(float2*)&dp[(size_t)r1 * F + n0]      = make_float2(c02, c03);
        *(float2*)&dp[(size_t)r1 * F + n0 + 8]  = make_float2(c12, c13);
        *(float2*)&dp[(size_t)r1 * F + n0 + 16] = make_float2(c22, c23);
        *(float2*)&dp[(size_t)r1 * F + n0 + 24] = make_float2(c32, c33);
    }
}

// ---------------- launch ----------------
extern "C" void kernel_launch(void* const* d_in, const int* in_sizes, int n_in,
                              void* d_out, int out_size) {
    const float* x  = (const float*)d_in[0];
    const void*  ei = d_in[1];
    const float* w1 = (const float*)d_in[2];
    const float* b1 = (const float*)d_in[3];
    const float* w2 = (const float*)d_in[4];
    const float* b2 = (const float*)d_in[5];
    float* out = (float*)d_out;

    int n = in_sizes[0] / F;     // 50000
    int e = in_sizes[1] / 2;     // 600000
    int nb = (n + 511) / 512;    // scan blocks (98)

    k_detect<<<1, 1024>>>((const unsigned int*)ei);

    // fold layers: W = W1^T W2^T, c = b1 W2^T + b2; pack B fragments
    k_prep_wc<<<F + 1, F>>>(w1, w2, b1, b2);
    k_prep_wf<<<32, 256>>>();

    // CSR by dst (counting sort, 3-phase parallel scan)
    k_zero_cnt<<<(n + 255) / 256, 256>>>(n);
    k_hist<<<(e + 255) / 256, 256>>>(ei, e, n);
    k_scan_block<<<nb, 512>>>(n);
    k_scan_top<<<1, 32>>>(nb, n);
    k_scan_add<<<nb, 512>>>(n);
    k_fill<<<(e + 255) / 256, 256>>>(ei, e, n);

    int conv_blocks = (n + GBM - 1) / GBM;

    // conv1: g_h = conv(x)    conv2+lsm: out = log_softmax(conv(g_h))
    k_conv<true,  false><<<conv_blocks, 512>>>(x, nullptr, n);
    k_conv<false, true ><<<conv_blocks, 512>>>(nullptr, out, n);
}

// round 9
// speedup vs baseline: 1.6667x; 1.0278x over previous
#include <cuda_runtime.h>
#include <stdint.h>

#define NN 50000
#define NE 600000
#define F  128
#define GBM 64

// ---------------- scratch (static device globals: no allocations) ----------
__device__ __align__(16) uint32_t g_Wf[16 * 16 * 32 * 2];// W = W1^T W2^T in mma B-fragment order (tf32)
__device__ __align__(16) float    g_c[F];                // combined bias c = b1 W2^T + b2
__device__ int   g_cnt[NN];                              // in-degree histogram (real edges)
__device__ int   g_rowstart[NN + 1];                     // CSR row offsets (by dst)
__device__ int   g_cursor[NN];                           // fill cursors
__device__ int   g_bsum[128];                            // per-block scan sums
__device__ int   g_sorted[NE];                           // src indices sorted by dst
__device__ __align__(16) float g_h[(size_t)NN * F];      // intermediate h1
__device__ int   d_is64;                                 // 1 if edge_index is int64

__device__ __forceinline__ uint32_t f2tf(float f) {
    uint32_t u;
    asm("cvt.rna.tf32.f32 %0, %1;" : "=r"(u) : "f"(f));
    return u;
}

__device__ __forceinline__ int load_idx(const void* ei, int e, int row, int i) {
    if (d_is64) return (int)((const long long*)ei)[(size_t)row * e + i];
    return ((const int*)ei)[row * e + i];
}

// ---------------- init: dtype detect (block 0) + zero histogram (blocks 1..) -
// int64 little-endian with values < 2^31 => every odd 32-bit word is 0.
__global__ void k_init(const unsigned int* __restrict__ w, int n) {
    if (blockIdx.x == 0) {
        __shared__ int nz;
        if (threadIdx.x == 0) nz = 0;
        __syncthreads();
        int local = 0;
        for (int i = threadIdx.x; i < 2048; i += blockDim.x)
            if (w[2 * i + 1] != 0u) local = 1;
        if (local) atomicOr(&nz, 1);
        __syncthreads();
        if (threadIdx.x == 0) d_is64 = (nz == 0) ? 1 : 0;
        return;
    }
    int i = (blockIdx.x - 1) * blockDim.x + threadIdx.x;
    if (i < n) g_cnt[i] = 0;
}

// ---------------- param prep: fold W1,W2 -> fragments directly; fold bias ----
// block k<F computes W[k][i] = sum_j w1[j][k] w2[i][j] and writes it straight
// into its tf32 B-fragment slot. block F folds the bias.
__global__ void k_prep_wcf(const float* __restrict__ w1, const float* __restrict__ w2,
                           const float* __restrict__ b1, const float* __restrict__ b2) {
    int i = threadIdx.x;
    if (blockIdx.x == F) {                      // bias block
        float s = b2[i];
#pragma unroll 4
        for (int j = 0; j < F; j++) s += b1[j] * w2[i * F + j];
        g_c[i] = s;
        return;
    }
    int k = blockIdx.x;
    float s = 0.f;
#pragma unroll 4
    for (int j = 0; j < F; j++) s += w1[j * F + k] * w2[i * F + j];
    // fragment slot: kc=k>>3, tig=k&3, slot=(k>>2)&1; nt=i>>3, gid=i&7, lane=gid*4+tig
    int idx = ((k >> 3) * 512 + (i >> 3) * 32 + (i & 7) * 4 + (k & 3)) * 2 + ((k >> 2) & 1);
    g_Wf[idx] = f2tf(s);
}

// ---------------- CSR build (counting sort by dst) ----------------
__global__ void k_hist(const void* __restrict__ ei, int e, int n) {
    int i = blockIdx.x * blockDim.x + threadIdx.x;
    if (i < e) {
        int dst = load_idx(ei, e, 1, i);
        if ((unsigned)dst < (unsigned)n) atomicAdd(&g_cnt[dst], 1);
    }
}

// phase 1: per-block (512) exclusive scan -> g_rowstart (local), total -> g_bsum
__global__ __launch_bounds__(512) void k_scan_block(int n) {
    __shared__ int wsum[16];
    int t = threadIdx.x, lane = t & 31, w = t >> 5;
    int gidx = blockIdx.x * 512 + t;
    int v = (gidx < n) ? g_cnt[gidx] : 0;
    int x = v;
#pragma unroll
    for (int o = 1; o < 32; o <<= 1) {
        int y = __shfl_up_sync(0xFFFFFFFFu, x, o);
        if (lane >= o) x += y;
    }
    if (lane == 31) wsum[w] = x;
    __syncthreads();
    if (w == 0 && lane < 16) {
        int s = wsum[lane];
#pragma unroll
        for (int o = 1; o < 16; o <<= 1) {
            int y = __shfl_up_sync(0xFFFFu, s, o);
            if (lane >= o) s += y;
        }
        wsum[lane] = s;
    }
    __syncthreads();
    int incl = x + (w > 0 ? wsum[w - 1] : 0);
    if (gidx < n) g_rowstart[gidx] = incl - v;
    if (t == 511) g_bsum[blockIdx.x] = incl;
}

// phase 2: each block recomputes its offset from the raw block sums (1 warp),
// adds it, inits cursors; block 0 also writes the grand total.
__global__ __launch_bounds__(512) void k_scan_add(int n, int nb) {
    __shared__ int off_s;
    int t = threadIdx.x;
    if (t < 32) {
        int acc = 0, tot = 0;
        for (int j = t; j < nb; j += 32) {
            int v = g_bsum[j];
            tot += v;
            if (j < blockIdx.x) acc += v;
        }
#pragma unroll
        for (int o = 16; o; o >>= 1) {
            acc += __shfl_xor_sync(0xFFFFFFFFu, acc, o);
            tot += __shfl_xor_sync(0xFFFFFFFFu, tot, o);
        }
        if (t == 0) {
            off_s = acc;
            if (blockIdx.x == 0) g_rowstart[n] = tot;
        }
    }
    __syncthreads();
    int gidx = blockIdx.x * 512 + t;
    if (gidx < n) {
        int v = g_rowstart[gidx] + off_s;
        g_rowstart[gidx] = v;
        g_cursor[gidx]   = v;
    }
}

__global__ void k_fill(const void* __restrict__ ei, int e, int n) {
    int i = blockIdx.x * blockDim.x + threadIdx.x;
    if (i < e) {
        int src = load_idx(ei, e, 0, i);
        int dst = load_idx(ei, e, 1, i);
        if ((unsigned)src < (unsigned)n && (unsigned)dst < (unsigned)n) {
            int p = atomicAdd(&g_cursor[dst], 1);
            g_sorted[p] = src;
        }
    }
}

// ---------------- fused conv: gather-agg + TF32 MMA + epilogue --------------
// 512 threads / 16 warps. Warp w: m-quadrant (w&3)*16 rows, n-quadrant (w>>2)*32 cols.
// FIRST : src = x (param),  dst = g_h.    else: src = g_h, dst = out (param).
// LSM   : apply row-wise log_softmax in the epilogue (cross-warp via smem).
#define MMA_TF32(c0, c1, c2, c3, bx, by)                                      \
    asm volatile(                                                             \
        "mma.sync.aligned.m16n8k8.row.col.f32.tf32.tf32.f32 "                 \
        "{%0,%1,%2,%3}, {%4,%5,%6,%7}, {%8,%9}, {%0,%1,%2,%3};"               \
        : "+f"(c0), "+f"(c1), "+f"(c2), "+f"(c3)                              \
        : "r"(a0), "r"(a1), "r"(a2), "r"(a3), "r"(bx), "r"(by))

template <bool FIRST, bool LSM>
__global__ __launch_bounds__(512) void k_conv(const float* __restrict__ src_param,
                                              float* __restrict__ dst_param, int M) {
    __shared__ uint32_t As[GBM * 132];   // 64 rows, pitch 132 words (bank = lane)
    __shared__ float sredm[GBM][4];      // per-row per-nquad max
    __shared__ float sreds[GBM][4];      // per-row per-nquad expsum
    int tid = threadIdx.x;
    int warp = tid >> 5, lane = tid & 31;
    int gid = lane >> 2, tig = lane & 3;
    int m0 = blockIdx.x * GBM;

    const float4* hv = FIRST ? (const float4*)src_param : (const float4*)g_h;
    float*        dp = FIRST ? g_h : dst_param;

    // ---- aggregation: warp handles rows [warp*4, warp*4+4), lane = 16B chunk
#pragma unroll
    for (int r = 0; r < 4; r++) {
        int row = warp * 4 + r;
        int gm  = m0 + row;
        float4 a = make_float4(0.f, 0.f, 0.f, 0.f);
        if (gm < M) {
            a = hv[(size_t)gm * 32 + lane];           // self loop
            int s = g_rowstart[gm], e2 = g_rowstart[gm + 1];
            int i = s;
            for (; i + 3 < e2; i += 4) {              // MLP=4
                int s0 = g_sorted[i],     s1 = g_sorted[i + 1];
                int s2 = g_sorted[i + 2], s3 = g_sorted[i + 3];
                float4 v0 = hv[(size_t)s0 * 32 + lane];
                float4 v1 = hv[(size_t)s1 * 32 + lane];
                float4 v2 = hv[(size_t)s2 * 32 + lane];
                float4 v3 = hv[(size_t)s3 * 32 + lane];
                a.x += (v0.x + v1.x) + (v2.x + v3.x);
                a.y += (v0.y + v1.y) + (v2.y + v3.y);
                a.z += (v0.z + v1.z) + (v2.z + v3.z);
                a.w += (v0.w + v1.w) + (v2.w + v3.w);
            }
            for (; i < e2; i++) {
                float4 v = hv[(size_t)g_sorted[i] * 32 + lane];
                a.x += v.x; a.y += v.y; a.z += v.z; a.w += v.w;
            }
        }
        uint4 t;
        t.x = f2tf(a.x); t.y = f2tf(a.y); t.z = f2tf(a.z); t.w = f2tf(a.w);
        *(uint4*)&As[row * 132 + lane * 4] = t;
    }
    __syncthreads();

    // ---- TF32 mma: quadrant (mrow0, 4 n-tiles starting at nt0)
    int mrow0 = (warp & 3) * 16;
    int nq    = warp >> 2;          // n-quadrant 0..3
    int nt0   = nq * 4;

    float c00 = 0.f, c01 = 0.f, c02 = 0.f, c03 = 0.f;
    float c10 = 0.f, c11 = 0.f, c12 = 0.f, c13 = 0.f;
    float c20 = 0.f, c21 = 0.f, c22 = 0.f, c23 = 0.f;
    float c30 = 0.f, c31 = 0.f, c32 = 0.f, c33 = 0.f;

    int abase = (mrow0 + gid) * 132;
    for (int kc = 0; kc < 16; kc++) {
        uint32_t a0 = As[abase + kc * 8 + tig];
        uint32_t a1 = As[abase + 8 * 132 + kc * 8 + tig];
        uint32_t a2 = As[abase + kc * 8 + tig + 4];
        uint32_t a3 = As[abase + 8 * 132 + kc * 8 + tig + 4];
        const uint2* wf = (const uint2*)g_Wf + (size_t)kc * 512 + nt0 * 32 + lane;
        uint2 b0 = wf[0];
        uint2 b1 = wf[32];
        uint2 b2 = wf[64];
        uint2 b3 = wf[96];
        MMA_TF32(c00, c01, c02, c03, b0.x, b0.y);
        MMA_TF32(c10, c11, c12, c13, b1.x, b1.y);
        MMA_TF32(c20, c21, c22, c23, b2.x, b2.y);
        MMA_TF32(c30, c31, c32, c33, b3.x, b3.y);
    }

    // ---- epilogue: bias (deg*c)
    int row0 = mrow0 + gid;          // in-block row of c?0,c?1
    int row1 = row0 + 8;             // in-block row of c?2,c?3
    int r0 = m0 + row0;
    int r1 = m0 + row1;
    float deg0 = (r0 < M) ? (float)(g_cnt[r0] + 1) : 0.f;
    float deg1 = (r1 < M) ? (float)(g_cnt[r1] + 1) : 0.f;
    int n0 = nt0 * 8 + 2 * tig;

    float w0 = g_c[n0],      w1 = g_c[n0 + 1];
    float w2 = g_c[n0 + 8],  w3 = g_c[n0 + 9];
    float w4 = g_c[n0 + 16], w5 = g_c[n0 + 17];
    float w6 = g_c[n0 + 24], w7 = g_c[n0 + 25];

    c00 += deg0 * w0; c01 += deg0 * w1; c10 += deg0 * w2; c11 += deg0 * w3;
    c20 += deg0 * w4; c21 += deg0 * w5; c30 += deg0 * w6; c31 += deg0 * w7;
    c02 += deg1 * w0; c03 += deg1 * w1; c12 += deg1 * w2; c13 += deg1 * w3;
    c22 += deg1 * w4; c23 += deg1 * w5; c32 += deg1 * w6; c33 += deg1 * w7;

    if (LSM) {
        float m0v = fmaxf(fmaxf(fmaxf(c00, c01), fmaxf(c10, c11)),
                          fmaxf(fmaxf(c20, c21), fmaxf(c30, c31)));
        float m1v = fmaxf(fmaxf(fmaxf(c02, c03), fmaxf(c12, c13)),
                          fmaxf(fmaxf(c22, c23), fmaxf(c32, c33)));
        m0v = fmaxf(m0v, __shfl_xor_sync(0xFFFFFFFFu, m0v, 1));
        m0v = fmaxf(m0v, __shfl_xor_sync(0xFFFFFFFFu, m0v, 2));
        m1v = fmaxf(m1v, __shfl_xor_sync(0xFFFFFFFFu, m1v, 1));
        m1v = fmaxf(m1v, __shfl_xor_sync(0xFFFFFFFFu, m1v, 2));
        if (tig == 0) { sredm[row0][nq] = m0v; sredm[row1][nq] = m1v; }
        __syncthreads();
        float rm0 = fmaxf(fmaxf(sredm[row0][0], sredm[row0][1]),
                          fmaxf(sredm[row0][2], sredm[row0][3]));
        float rm1 = fmaxf(fmaxf(sredm[row1][0], sredm[row1][1]),
                          fmaxf(sredm[row1][2], sredm[row1][3]));
        float s0 = __expf(c00 - rm0) + __expf(c01 - rm0) + __expf(c10 - rm0) +
                   __expf(c11 - rm0) + __expf(c20 - rm0) + __expf(c21 - rm0) +
                   __expf(c30 - rm0) + __expf(c31 - rm0);
        float s1 = __expf(c02 - rm1) + __expf(c03 - rm1) + __expf(c12 - rm1) +
                   __expf(c13 - rm1) + __expf(c22 - rm1) + __expf(c23 - rm1) +
                   __expf(c32 - rm1) + __expf(c33 - rm1);
        s0 += __shfl_xor_sync(0xFFFFFFFFu, s0, 1);
        s0 += __shfl_xor_sync(0xFFFFFFFFu, s0, 2);
        s1 += __shfl_xor_sync(0xFFFFFFFFu, s1, 1);
        s1 += __shfl_xor_sync(0xFFFFFFFFu, s1, 2);
        if (tig == 0) { sreds[row0][nq] = s0; sreds[row1][nq] = s1; }
        __syncthreads();
        float t0 = (sreds[row0][0] + sreds[row0][1]) + (sreds[row0][2] + sreds[row0][3]);
        float t1 = (sreds[row1][0] + sreds[row1][1]) + (sreds[row1][2] + sreds[row1][3]);
        float l0 = rm0 + __logf(t0);
        float l1 = rm1 + __logf(t1);
        c00 -= l0; c01 -= l0; c10 -= l0; c11 -= l0;
        c20 -= l0; c21 -= l0; c30 -= l0; c31 -= l0;
        c02 -= l1; c03 -= l1; c12 -= l1; c13 -= l1;
        c22 -= l1; c23 -= l1; c32 -= l1; c33 -= l1;
    }

    if (r0 < M) {
        *(float2*)&dp[(size_t)r0 * F + n0]      = make_float2(c00, c01);
        *(float2*)&dp[(size_t)r0 * F + n0 + 8]  = make_float2(c10, c11);
        *(float2*)&dp[(size_t)r0 * F + n0 + 16] = make_float2(c20, c21);
        *(float2*)&dp[(size_t)r0 * F + n0 + 24] = make_float2(c30, c31);
    }
    if (r1 < M) {
        *(float2*)&dp[(size_t)r1 * F + n0]      = make_float2(c02, c03);
        *(float2*)&dp[(size_t)r1 * F + n0 + 8]  = make_float2(c12, c13);
        *(float2*)&dp[(size_t)r1 * F + n0 + 16] = make_float2(c22, c23);
        *(float2*)&dp[(size_t)r1 * F + n0 + 24] = make_float2(c32, c33);
    }
}

// ---------------- launch ----------------
extern "C" void kernel_launch(void* const* d_in, const int* in_sizes, int n_in,
                              void* d_out, int out_size) {
    const float* x  = (const float*)d_in[0];
    const void*  ei = d_in[1];
    const float* w1 = (const float*)d_in[2];
    const float* b1 = (const float*)d_in[3];
    const float* w2 = (const float*)d_in[4];
    const float* b2 = (const float*)d_in[5];
    float* out = (float*)d_out;

    int n = in_sizes[0] / F;     // 50000
    int e = in_sizes[1] / 2;     // 600000
    int nb = (n + 511) / 512;    // scan blocks (98)

    // detect dtype + zero histogram (one launch)
    k_init<<<(n + 255) / 256 + 1, 256>>>((const unsigned int*)ei, n);

    // fold layers straight into tf32 fragments + fold bias (one launch)
    k_prep_wcf<<<F + 1, F>>>(w1, w2, b1, b2);

    // CSR by dst (counting sort, 2-phase scan)
    k_hist<<<(e + 255) / 256, 256>>>(ei, e, n);
    k_scan_block<<<nb, 512>>>(n);
    k_scan_add<<<nb, 512>>>(n, nb);
    k_fill<<<(e + 255) / 256, 256>>>(ei, e, n);

    int conv_blocks = (n + GBM - 1) / GBM;

    // conv1: g_h = conv(x)    conv2+lsm: out = log_softmax(conv(g_h))
    k_conv<true,  false><<<conv_blocks, 512>>>(x, nullptr, n);
    k_conv<false, true ><<<conv_blocks, 512>>>(nullptr, out, n);
}

// round 10
// speedup vs baseline: 1.6901x; 1.0141x over previous
#include <cuda_runtime.h>
#include <stdint.h>

#define NN 50000
#define NE 600000
#define F  128
#define GBM 32

// ---------------- scratch (static device globals: no allocations) ----------
__device__ __align__(16) uint32_t g_Wf[16 * 16 * 32 * 2];// W = W1^T W2^T in mma B-fragment order (tf32)
__device__ __align__(16) float    g_c[F];                // combined bias c = b1 W2^T + b2
__device__ int   g_cnt[NN];                              // in-degree histogram (real edges)
__device__ int   g_rowstart[NN + 1];                     // CSR row offsets (by dst)
__device__ int   g_cursor[NN];                           // fill cursors
__device__ int   g_bsum[128];                            // per-block scan sums
__device__ int   g_sorted[NE];                           // src indices sorted by dst
__device__ __align__(16) float g_h[(size_t)NN * F];      // intermediate h1
__device__ int   d_is64;                                 // 1 if edge_index is int64

__device__ __forceinline__ uint32_t f2tf(float f) {
    uint32_t u;
    asm("cvt.rna.tf32.f32 %0, %1;" : "=r"(u) : "f"(f));
    return u;
}

// 32-bit index load: for int64 (little-endian, values < 2^31) read the low word.
__device__ __forceinline__ int load_idx(const void* ei, int e, int row, int i) {
    const int* p = (const int*)ei;
    if (d_is64) return p[2 * ((size_t)row * e + i)];
    return p[row * e + i];
}

// ---------------- init: dtype detect (block 0) + zero histogram (blocks 1..) -
// int64 little-endian with values < 2^31 => every odd 32-bit word is 0.
__global__ void k_init(const unsigned int* __restrict__ w, int n) {
    if (blockIdx.x == 0) {
        __shared__ int nz;
        if (threadIdx.x == 0) nz = 0;
        __syncthreads();
        int local = 0;
        for (int i = threadIdx.x; i < 2048; i += blockDim.x)
            if (w[2 * i + 1] != 0u) local = 1;
        if (local) atomicOr(&nz, 1);
        __syncthreads();
        if (threadIdx.x == 0) d_is64 = (nz == 0) ? 1 : 0;
        return;
    }
    int i = (blockIdx.x - 1) * blockDim.x + threadIdx.x;
    if (i < n) g_cnt[i] = 0;
}

// ---------------- param prep: fold W1,W2 -> fragments directly; fold bias ----
__global__ void k_prep_wcf(const float* __restrict__ w1, const float* __restrict__ w2,
                           const float* __restrict__ b1, const float* __restrict__ b2) {
    int i = threadIdx.x;
    if (blockIdx.x == F) {                      // bias block
        float s = b2[i];
#pragma unroll 4
        for (int j = 0; j < F; j++) s += b1[j] * w2[i * F + j];
        g_c[i] = s;
        return;
    }
    int k = blockIdx.x;
    float s = 0.f;
#pragma unroll 4
    for (int j = 0; j < F; j++) s += w1[j * F + k] * w2[i * F + j];
    // fragment slot: kc=k>>3, tig=k&3, slot=(k>>2)&1; nt=i>>3, gid=i&7, lane=gid*4+tig
    int idx = ((k >> 3) * 512 + (i >> 3) * 32 + (i & 7) * 4 + (k & 3)) * 2 + ((k >> 2) & 1);
    g_Wf[idx] = f2tf(s);
}

// ---------------- CSR build (counting sort by dst) ----------------
__global__ void k_hist(const void* __restrict__ ei, int e, int n) {
    int i = blockIdx.x * blockDim.x + threadIdx.x;
    if (i < e) {
        int dst = load_idx(ei, e, 1, i);
        if ((unsigned)dst < (unsigned)n) atomicAdd(&g_cnt[dst], 1);
    }
}

// phase 1: per-block (512) exclusive scan -> g_rowstart (local), total -> g_bsum
__global__ __launch_bounds__(512) void k_scan_block(int n) {
    __shared__ int wsum[16];
    int t = threadIdx.x, lane = t & 31, w = t >> 5;
    int gidx = blockIdx.x * 512 + t;
    int v = (gidx < n) ? g_cnt[gidx] : 0;
    int x = v;
#pragma unroll
    for (int o = 1; o < 32; o <<= 1) {
        int y = __shfl_up_sync(0xFFFFFFFFu, x, o);
        if (lane >= o) x += y;
    }
    if (lane == 31) wsum[w] = x;
    __syncthreads();
    if (w == 0 && lane < 16) {
        int s = wsum[lane];
#pragma unroll
        for (int o = 1; o < 16; o <<= 1) {
            int y = __shfl_up_sync(0xFFFFu, s, o);
            if (lane >= o) s += y;
        }
        wsum[lane] = s;
    }
    __syncthreads();
    int incl = x + (w > 0 ? wsum[w - 1] : 0);
    if (gidx < n) g_rowstart[gidx] = incl - v;
    if (t == 511) g_bsum[blockIdx.x] = incl;
}

// phase 2: each block recomputes its offset from the raw block sums (1 warp),
// adds it, inits cursors; block 0 also writes the grand total.
__global__ __launch_bounds__(512) void k_scan_add(int n, int nb) {
    __shared__ int off_s;
    int t = threadIdx.x;
    if (t < 32) {
        int acc = 0, tot = 0;
        for (int j = t; j < nb; j += 32) {
            int v = g_bsum[j];
            tot += v;
            if (j < blockIdx.x) acc += v;
        }
#pragma unroll
        for (int o = 16; o; o >>= 1) {
            acc += __shfl_xor_sync(0xFFFFFFFFu, acc, o);
            tot += __shfl_xor_sync(0xFFFFFFFFu, tot, o);
        }
        if (t == 0) {
            off_s = acc;
            if (blockIdx.x == 0) g_rowstart[n] = tot;
        }
    }
    __syncthreads();
    int gidx = blockIdx.x * 512 + t;
    if (gidx < n) {
        int v = g_rowstart[gidx] + off_s;
        g_rowstart[gidx] = v;
        g_cursor[gidx]   = v;
    }
}

__global__ void k_fill(const void* __restrict__ ei, int e, int n) {
    int i = blockIdx.x * blockDim.x + threadIdx.x;
    if (i < e) {
        int src = load_idx(ei, e, 0, i);
        int dst = load_idx(ei, e, 1, i);
        if ((unsigned)src < (unsigned)n && (unsigned)dst < (unsigned)n) {
            int p = atomicAdd(&g_cursor[dst], 1);
            g_sorted[p] = src;
        }
    }
}

// ---------------- fused conv: gather-agg + TF32 MMA + epilogue --------------
// GBM=32 rows/block, 256 threads / 8 warps: warp w -> m-half (w&1)*16 rows,
// n-quadrant (w>>1)*32 cols. 4 gather rows/warp. 16 named scalar accumulators.
// ~17KB smem -> 4 CTAs/SM: gather(L2) phase of one CTA overlaps MMA(tensor)
// phase of its neighbors.
#define MMA_TF32(c0, c1, c2, c3, bx, by)                                      \
    asm volatile(                                                             \
        "mma.sync.aligned.m16n8k8.row.col.f32.tf32.tf32.f32 "                 \
        "{%0,%1,%2,%3}, {%4,%5,%6,%7}, {%8,%9}, {%0,%1,%2,%3};"               \
        : "+f"(c0), "+f"(c1), "+f"(c2), "+f"(c3)                              \
        : "r"(a0), "r"(a1), "r"(a2), "r"(a3), "r"(bx), "r"(by))

template <bool FIRST, bool LSM>
__global__ __launch_bounds__(256) void k_conv(const float* __restrict__ src_param,
                                              float* __restrict__ dst_param, int M) {
    __shared__ uint32_t As[GBM * 132];   // 32 rows, pitch 132 words (bank = lane)
    __shared__ float sredm[GBM][4];      // per-row per-nquad max
    __shared__ float sreds[GBM][4];      // per-row per-nquad expsum
    int tid = threadIdx.x;
    int warp = tid >> 5, lane = tid & 31;
    int gid = lane >> 2, tig = lane & 3;
    int m0 = blockIdx.x * GBM;

    const float4* hv = FIRST ? (const float4*)src_param : (const float4*)g_h;
    float*        dp = FIRST ? g_h : dst_param;

    // ---- aggregation: warp handles rows [warp*4, warp*4+4), lane = 16B chunk
#pragma unroll
    for (int r = 0; r < 4; r++) {
        int row = warp * 4 + r;
        int gm  = m0 + row;
        float4 a = make_float4(0.f, 0.f, 0.f, 0.f);
        if (gm < M) {
            a = hv[(size_t)gm * 32 + lane];           // self loop
            int s = g_rowstart[gm], e2 = g_rowstart[gm + 1];
            int i = s;
            for (; i + 3 < e2; i += 4) {              // MLP=4
                int s0 = g_sorted[i],     s1 = g_sorted[i + 1];
                int s2 = g_sorted[i + 2], s3 = g_sorted[i + 3];
                float4 v0 = hv[(size_t)s0 * 32 + lane];
                float4 v1 = hv[(size_t)s1 * 32 + lane];
                float4 v2 = hv[(size_t)s2 * 32 + lane];
                float4 v3 = hv[(size_t)s3 * 32 + lane];
                a.x += (v0.x + v1.x) + (v2.x + v3.x);
                a.y += (v0.y + v1.y) + (v2.y + v3.y);
                a.z += (v0.z + v1.z) + (v2.z + v3.z);
                a.w += (v0.w + v1.w) + (v2.w + v3.w);
            }
            for (; i < e2; i++) {
                float4 v = hv[(size_t)g_sorted[i] * 32 + lane];
                a.x += v.x; a.y += v.y; a.z += v.z; a.w += v.w;
            }
        }
        uint4 t;
        t.x = f2tf(a.x); t.y = f2tf(a.y); t.z = f2tf(a.z); t.w = f2tf(a.w);
        *(uint4*)&As[row * 132 + lane * 4] = t;
    }
    __syncthreads();

    // ---- TF32 mma: m-half mrow0, 4 n-tiles starting at nt0
    int mrow0 = (warp & 1) * 16;
    int nq    = warp >> 1;          // n-quadrant 0..3
    int nt0   = nq * 4;

    float c00 = 0.f, c01 = 0.f, c02 = 0.f, c03 = 0.f;
    float c10 = 0.f, c11 = 0.f, c12 = 0.f, c13 = 0.f;
    float c20 = 0.f, c21 = 0.f, c22 = 0.f, c23 = 0.f;
    float c30 = 0.f, c31 = 0.f, c32 = 0.f, c33 = 0.f;

    int abase = (mrow0 + gid) * 132;
    for (int kc = 0; kc < 16; kc++) {
        uint32_t a0 = As[abase + kc * 8 + tig];
        uint32_t a1 = As[abase + 8 * 132 + kc * 8 + tig];
        uint32_t a2 = As[abase + kc * 8 + tig + 4];
        uint32_t a3 = As[abase + 8 * 132 + kc * 8 + tig + 4];
        const uint2* wf = (const uint2*)g_Wf + (size_t)kc * 512 + nt0 * 32 + lane;
        uint2 b0 = wf[0];
        uint2 b1 = wf[32];
        uint2 b2 = wf[64];
        uint2 b3 = wf[96];
        MMA_TF32(c00, c01, c02, c03, b0.x, b0.y);
        MMA_TF32(c10, c11, c12, c13, b1.x, b1.y);
        MMA_TF32(c20, c21, c22, c23, b2.x, b2.y);
        MMA_TF32(c30, c31, c32, c33, b3.x, b3.y);
    }

    // ---- epilogue: bias (deg*c)
    int row0 = mrow0 + gid;          // in-block row of c?0,c?1
    int row1 = row0 + 8;             // in-block row of c?2,c?3
    int r0 = m0 + row0;
    int r1 = m0 + row1;
    float deg0 = (r0 < M) ? (float)(g_cnt[r0] + 1) : 0.f;
    float deg1 = (r1 < M) ? (float)(g_cnt[r1] + 1) : 0.f;
    int n0 = nt0 * 8 + 2 * tig;

    float w0 = g_c[n0],      w1 = g_c[n0 + 1];
    float w2 = g_c[n0 + 8],  w3 = g_c[n0 + 9];
    float w4 = g_c[n0 + 16], w5 = g_c[n0 + 17];
    float w6 = g_c[n0 + 24], w7 = g_c[n0 + 25];

    c00 += deg0 * w0; c01 += deg0 * w1; c10 += deg0 * w2; c11 += deg0 * w3;
    c20 += deg0 * w4; c21 += deg0 * w5; c30 += deg0 * w6; c31 += deg0 * w7;
    c02 += deg1 * w0; c03 += deg1 * w1; c12 += deg1 * w2; c13 += deg1 * w3;
    c22 += deg1 * w4; c23 += deg1 * w5; c32 += deg1 * w6; c33 += deg1 * w7;

    if (LSM) {
        float m0v = fmaxf(fmaxf(fmaxf(c00, c01), fmaxf(c10, c11)),
                          fmaxf(fmaxf(c20, c21), fmaxf(c30, c31)));
        float m1v = fmaxf(fmaxf(fmaxf(c02, c03), fmaxf(c12, c13)),
                          fmaxf(fmaxf(c22, c23), fmaxf(c32, c33)));
        m0v = fmaxf(m0v, __shfl_xor_sync(0xFFFFFFFFu, m0v, 1));
        m0v = fmaxf(m0v, __shfl_xor_sync(0xFFFFFFFFu, m0v, 2));
        m1v = fmaxf(m1v, __shfl_xor_sync(0xFFFFFFFFu, m1v, 1));
        m1v = fmaxf(m1v, __shfl_xor_sync(0xFFFFFFFFu, m1v, 2));
        if (tig == 0) { sredm[row0][nq] = m0v; sredm[row1][nq] = m1v; }
        __syncthreads();
        float rm0 = fmaxf(fmaxf(sredm[row0][0], sredm[row0][1]),
                          fmaxf(sredm[row0][2], sredm[row0][3]));
        float rm1 = fmaxf(fmaxf(sredm[row1][0], sredm[row1][1]),
                          fmaxf(sredm[row1][2], sredm[row1][3]));
        float s0 = __expf(c00 - rm0) + __expf(c01 - rm0) + __expf(c10 - rm0) +
                   __expf(c11 - rm0) + __expf(c20 - rm0) + __expf(c21 - rm0) +
                   __expf(c30 - rm0) + __expf(c31 - rm0);
        float s1 = __expf(c02 - rm1) + __expf(c03 - rm1) + __expf(c12 - rm1) +
                   __expf(c13 - rm1) + __expf(c22 - rm1) + __expf(c23 - rm1) +
                   __expf(c32 - rm1) + __expf(c33 - rm1);
        s0 += __shfl_xor_sync(0xFFFFFFFFu, s0, 1);
        s0 += __shfl_xor_sync(0xFFFFFFFFu, s0, 2);
        s1 += __shfl_xor_sync(0xFFFFFFFFu, s1, 1);
        s1 += __shfl_xor_sync(0xFFFFFFFFu, s1, 2);
        if (tig == 0) { sreds[row0][nq] = s0; sreds[row1][nq] = s1; }
        __syncthreads();
        float t0 = (sreds[row0][0] + sreds[row0][1]) + (sreds[row0][2] + sreds[row0][3]);
        float t1 = (sreds[row1][0] + sreds[row1][1]) + (sreds[row1][2] + sreds[row1][3]);
        float l0 = rm0 + __logf(t0);
        float l1 = rm1 + __logf(t1);
        c00 -= l0; c01 -= l0; c10 -= l0; c11 -= l0;
        c20 -= l0; c21 -= l0; c30 -= l0; c31 -= l0;
        c02 -= l1; c03 -= l1; c12 -= l1; c13 -= l1;
        c22 -= l1; c23 -= l1; c32 -= l1; c33 -= l1;
    }

    if (r0 < M) {
        *(float2*)&dp[(size_t)r0 * F + n0]      = make_float2(c00, c01);
        *(float2*)&dp[(size_t)r0 * F + n0 + 8]  = make_float2(c10, c11);
        *(float2*)&dp[(size_t)r0 * F + n0 + 16] = make_float2(c20, c21);
        *(float2*)&dp[(size_t)r0 * F + n0 + 24] = make_float2(c30, c31);
    }
    if (r1 < M) {
        *(float2*)&dp[(size_t)r1 * F + n0]      = make_float2(c02, c03);
        *(float2*)&dp[(size_t)r1 * F + n0 + 8]  = make_float2(c12, c13);
        *(float2*)&dp[(size_t)r1 * F + n0 + 16] = make_float2(c22, c23);
        *(float2*)&dp[(size_t)r1 * F + n0 + 24] = make_float2(c32, c33);
    }
}

// ---------------- launch ----------------
extern "C" void kernel_launch(void* const* d_in, const int* in_sizes, int n_in,
                              void* d_out, int out_size) {
    const float* x  = (const float*)d_in[0];
    const void*  ei = d_in[1];
    const float* w1 = (const float*)d_in[2];
    const float* b1 = (const float*)d_in[3];
    const float* w2 = (const float*)d_in[4];
    const float* b2 = (const float*)d_in[5];
    float* out = (float*)d_out;

    int n = in_sizes[0] / F;     // 50000
    int e = in_sizes[1] / 2;     // 600000
    int nb = (n + 511) / 512;    // scan blocks (98)

    // detect dtype + zero histogram (one launch)
    k_init<<<(n + 255) / 256 + 1, 256>>>((const unsigned int*)ei, n);

    // fold layers straight into tf32 fragments + fold bias (one launch)
    k_prep_wcf<<<F + 1, F>>>(w1, w2, b1, b2);

    // CSR by dst (counting sort, 2-phase scan)
    k_hist<<<(e + 255) / 256, 256>>>(ei, e, n);
    k_scan_block<<<nb, 512>>>(n);
    k_scan_add<<<nb, 512>>>(n, nb);
    k_fill<<<(e + 255) / 256, 256>>>(ei, e, n);

    int conv_blocks = (n + GBM - 1) / GBM;

    // conv1: g_h = conv(x)    conv2+lsm: out = log_softmax(conv(g_h))
    k_conv<true,  false><<<conv_blocks, 256>>>(x, nullptr, n);
    k_conv<false, true ><<<conv_blocks, 256>>>(nullptr, out, n);
}

// round 13
// speedup vs baseline: 1.7147x; 1.0145x over previous
#include <cuda_runtime.h>
#include <cuda_fp16.h>
#include <stdint.h>
#include <string.h>

#define NN 50000
#define NE 600000
#define F  128
#define GBM 32

// ---------------- scratch (static device globals: no allocations) ----------
__device__ __align__(16) uint32_t g_Wf[16 * 16 * 32 * 2];// W = W1^T W2^T in mma B-fragment order (tf32)
__device__ __align__(16) float    g_c[F];                // combined bias c = b1 W2^T + b2
__device__ int   g_cnt[NN];                              // in-degree histogram (real edges)
__device__ int   g_rowstart[NN + 1];                     // CSR row offsets (by dst)
__device__ int   g_cursor[NN];                           // fill cursors
__device__ int   g_bsum[128];                            // per-block scan sums
__device__ int   g_sorted[NE];                           // src indices sorted by dst
__device__ __align__(16) uint32_t g_xh[(size_t)NN * F / 2]; // x in fp16 (packed half2)
__device__ __align__(16) uint32_t g_hh[(size_t)NN * F / 2]; // h1 in fp16 (packed half2)
__device__ int   d_is64;                                 // 1 if edge_index is int64

__device__ __forceinline__ uint32_t f2tf(float f) {
    uint32_t u;
    asm("cvt.rna.tf32.f32 %0, %1;" : "=r"(u) : "f"(f));
    return u;
}

// bit-pun __half2 -> uint32 (nvcc folds the memcpy to a register move)
__device__ __forceinline__ uint32_t h2u(__half2 h) {
    uint32_t u;
    memcpy(&u, &h, 4);
    return u;
}

// 32-bit index load: for int64 (little-endian, values < 2^31) read the low word.
__device__ __forceinline__ int load_idx(const void* ei, int e, int row, int i) {
    const int* p = (const int*)ei;
    if (d_is64) return p[2 * ((size_t)row * e + i)];
    return p[row * e + i];
}

// ---------------- init: detect dtype (blk 0) + zero hist + convert x->fp16 --
__global__ void k_init(const unsigned int* __restrict__ w,
                       const float4* __restrict__ x4, int n) {
    if (blockIdx.x == 0) {
        __shared__ int nz;
        if (threadIdx.x == 0) nz = 0;
        __syncthreads();
        int local = 0;
        for (int i = threadIdx.x; i < 2048; i += blockDim.x)
            if (w[2 * i + 1] != 0u) local = 1;
        if (local) atomicOr(&nz, 1);
        __syncthreads();
        if (threadIdx.x == 0) d_is64 = (nz == 0) ? 1 : 0;
        return;
    }
    int i = (blockIdx.x - 1) * blockDim.x + threadIdx.x;
    if (i < n) g_cnt[i] = 0;
    // grid-stride fp16 conversion of x: 8 floats -> one uint4 of half2s
    int total = n * (F / 8);
    int stride = (gridDim.x - 1) * blockDim.x;
    for (int idx = i; idx < total; idx += stride) {
        float4 v0 = x4[idx * 2];
        float4 v1 = x4[idx * 2 + 1];
        uint4 o;
        o.x = h2u(__floats2half2_rn(v0.x, v0.y));
        o.y = h2u(__floats2half2_rn(v0.z, v0.w));
        o.z = h2u(__floats2half2_rn(v1.x, v1.y));
        o.w = h2u(__floats2half2_rn(v1.z, v1.w));
        ((uint4*)g_xh)[idx] = o;
    }
}

// ---------------- param prep: fold W1,W2 -> fragments directly; fold bias ----
__global__ void k_prep_wcf(const float* __restrict__ w1, const float* __restrict__ w2,
                           const float* __restrict__ b1, const float* __restrict__ b2) {
    int i = threadIdx.x;
    if (blockIdx.x == F) {                      // bias block
        float s = b2[i];
#pragma unroll 4
        for (int j = 0; j < F; j++) s += b1[j] * w2[i * F + j];
        g_c[i] = s;
        return;
    }
    int k = blockIdx.x;
    float s = 0.f;
#pragma unroll 4
    for (int j = 0; j < F; j++) s += w1[j * F + k] * w2[i * F + j];
    // fragment slot: kc=k>>3, tig=k&3, slot=(k>>2)&1; nt=i>>3, gid=i&7, lane=gid*4+tig
    int idx = ((k >> 3) * 512 + (i >> 3) * 32 + (i & 7) * 4 + (k & 3)) * 2 + ((k >> 2) & 1);
    g_Wf[idx] = f2tf(s);
}

// ---------------- CSR build (counting sort by dst) ----------------
__global__ void k_hist(const void* __restrict__ ei, int e, int n) {
    int i = blockIdx.x * blockDim.x + threadIdx.x;
    if (i < e) {
        int dst = load_idx(ei, e, 1, i);
        if ((unsigned)dst < (unsigned)n) atomicAdd(&g_cnt[dst], 1);
    }
}

__global__ __launch_bounds__(512) void k_scan_block(int n) {
    __shared__ int wsum[16];
    int t = threadIdx.x, lane = t & 31, w = t >> 5;
    int gidx = blockIdx.x * 512 + t;
    int v = (gidx < n) ? g_cnt[gidx] : 0;
    int x = v;
#pragma unroll
    for (int o = 1; o < 32; o <<= 1) {
        int y = __shfl_up_sync(0xFFFFFFFFu, x, o);
        if (lane >= o) x += y;
    }
    if (lane == 31) wsum[w] = x;
    __syncthreads();
    if (w == 0 && lane < 16) {
        int s = wsum[lane];
#pragma unroll
        for (int o = 1; o < 16; o <<= 1) {
            int y = __shfl_up_sync(0xFFFFu, s, o);
            if (lane >= o) s += y;
        }
        wsum[lane] = s;
    }
    __syncthreads();
    int incl = x + (w > 0 ? wsum[w - 1] : 0);
    if (gidx < n) g_rowstart[gidx] = incl - v;
    if (t == 511) g_bsum[blockIdx.x] = incl;
}

__global__ __launch_bounds__(512) void k_scan_add(int n, int nb) {
    __shared__ int off_s;
    int t = threadIdx.x;
    if (t < 32) {
        int acc = 0, tot = 0;
        for (int j = t; j < nb; j += 32) {
            int v = g_bsum[j];
            tot += v;
            if (j < blockIdx.x) acc += v;
        }
#pragma unroll
        for (int o = 16; o; o >>= 1) {
            acc += __shfl_xor_sync(0xFFFFFFFFu, acc, o);
            tot += __shfl_xor_sync(0xFFFFFFFFu, tot, o);
        }
        if (t == 0) {
            off_s = acc;
            if (blockIdx.x == 0) g_rowstart[n] = tot;
        }
    }
    __syncthreads();
    int gidx = blockIdx.x * 512 + t;
    if (gidx < n) {
        int v = g_rowstart[gidx] + off_s;
        g_rowstart[gidx] = v;
        g_cursor[gidx]   = v;
    }
}

__global__ void k_fill(const void* __restrict__ ei, int e, int n) {
    int i = blockIdx.x * blockDim.x + threadIdx.x;
    if (i < e) {
        int src = load_idx(ei, e, 0, i);
        int dst = load_idx(ei, e, 1, i);
        if ((unsigned)src < (unsigned)n && (unsigned)dst < (unsigned)n) {
            int p = atomicAdd(&g_cursor[dst], 1);
            g_sorted[p] = src;
        }
    }
}

// ---------------- fused conv: fp16 gather-agg + TF32 MMA + epilogue ---------
// GBM=32 rows/block, 256 threads / 8 warps: warp w -> m-half (w&1)*16 rows,
// n-quadrant (w>>1)*32 cols. Rows gathered as fp16: one row = 128 halfs =
// 32 uint2 chunks (row stride 32!), lane owns uint2 = features lane*4..+3.
#define MMA_TF32(c0, c1, c2, c3, bx, by)                                      \
    asm volatile(                                                             \
        "mma.sync.aligned.m16n8k8.row.col.f32.tf32.tf32.f32 "                 \
        "{%0,%1,%2,%3}, {%4,%5,%6,%7}, {%8,%9}, {%0,%1,%2,%3};"               \
        : "+f"(c0), "+f"(c1), "+f"(c2), "+f"(c3)                              \
        : "r"(a0), "r"(a1), "r"(a2), "r"(a3), "r"(bx), "r"(by))

template <bool FIRST, bool LSM>
__global__ __launch_bounds__(256) void k_conv(float* __restrict__ dst_param, int M) {
    __shared__ uint32_t As[GBM * 132];   // 32 rows, pitch 132 words (bank = lane)
    __shared__ float sredm[GBM][4];
    __shared__ float sreds[GBM][4];
    int tid = threadIdx.x;
    int warp = tid >> 5, lane = tid & 31;
    int gid = lane >> 2, tig = lane & 3;
    int m0 = blockIdx.x * GBM;

    const uint2* hv = FIRST ? (const uint2*)g_xh : (const uint2*)g_hh;

    // ---- aggregation: warp handles rows [warp*4, warp*4+4), lane = 8B chunk
#pragma unroll
    for (int r = 0; r < 4; r++) {
        int row = warp * 4 + r;
        int gm  = m0 + row;
        float ax = 0.f, ay = 0.f, az = 0.f, aw = 0.f;
        if (gm < M) {
            uint2 u = hv[(size_t)gm * 32 + lane];     // self loop
            float2 p0 = __half22float2(*(__half2*)&u.x);
            float2 p1 = __half22float2(*(__half2*)&u.y);
            ax = p0.x; ay = p0.y; az = p1.x; aw = p1.y;
            int s = g_rowstart[gm], e2 = g_rowstart[gm + 1];
            int i = s;
            for (; i + 3 < e2; i += 4) {              // MLP=4
                int s0 = g_sorted[i],     s1 = g_sorted[i + 1];
                int s2 = g_sorted[i + 2], s3 = g_sorted[i + 3];
                uint2 u0 = hv[(size_t)s0 * 32 + lane];
                uint2 u1 = hv[(size_t)s1 * 32 + lane];
                uint2 u2 = hv[(size_t)s2 * 32 + lane];
                uint2 u3 = hv[(size_t)s3 * 32 + lane];
                float2 q;
                q = __half22float2(*(__half2*)&u0.x); ax += q.x; ay += q.y;
                q = __half22float2(*(__half2*)&u0.y); az += q.x; aw += q.y;
                q = __half22float2(*(__half2*)&u1.x); ax += q.x; ay += q.y;
                q = __half22float2(*(__half2*)&u1.y); az += q.x; aw += q.y;
                q = __half22float2(*(__half2*)&u2.x); ax += q.x; ay += q.y;
                q = __half22float2(*(__half2*)&u2.y); az += q.x; aw += q.y;
                q = __half22float2(*(__half2*)&u3.x); ax += q.x; ay += q.y;
                q = __half22float2(*(__half2*)&u3.y); az += q.x; aw += q.y;
            }
            for (; i < e2; i++) {
                uint2 u4 = hv[(size_t)g_sorted[i] * 32 + lane];
                float2 q;
                q = __half22float2(*(__half2*)&u4.x); ax += q.x; ay += q.y;
                q = __half22float2(*(__half2*)&u4.y); az += q.x; aw += q.y;
            }
        }
        uint4 t;
        t.x = f2tf(ax); t.y = f2tf(ay); t.z = f2tf(az); t.w = f2tf(aw);
        *(uint4*)&As[row * 132 + lane * 4] = t;
    }
    __syncthreads();

    // ---- TF32 mma: m-half mrow0, 4 n-tiles starting at nt0
    int mrow0 = (warp & 1) * 16;
    int nq    = warp >> 1;
    int nt0   = nq * 4;

    float c00 = 0.f, c01 = 0.f, c02 = 0.f, c03 = 0.f;
    float c10 = 0.f, c11 = 0.f, c12 = 0.f, c13 = 0.f;
    float c20 = 0.f, c21 = 0.f, c22 = 0.f, c23 = 0.f;
    float c30 = 0.f, c31 = 0.f, c32 = 0.f, c33 = 0.f;

    int abase = (mrow0 + gid) * 132;
    for (int kc = 0; kc < 16; kc++) {
        uint32_t a0 = As[abase + kc * 8 + tig];
        uint32_t a1 = As[abase + 8 * 132 + kc * 8 + tig];
        uint32_t a2 = As[abase + kc * 8 + tig + 4];
        uint32_t a3 = As[abase + 8 * 132 + kc * 8 + tig + 4];
        const uint2* wf = (const uint2*)g_Wf + (size_t)kc * 512 + nt0 * 32 + lane;
        uint2 b0 = wf[0];
        uint2 b1 = wf[32];
        uint2 b2 = wf[64];
        uint2 b3 = wf[96];
        MMA_TF32(c00, c01, c02, c03, b0.x, b0.y);
        MMA_TF32(c10, c11, c12, c13, b1.x, b1.y);
        MMA_TF32(c20, c21, c22, c23, b2.x, b2.y);
        MMA_TF32(c30, c31, c32, c33, b3.x, b3.y);
    }

    // ---- epilogue: bias (deg*c)
    int row0 = mrow0 + gid;
    int row1 = row0 + 8;
    int r0 = m0 + row0;
    int r1 = m0 + row1;
    float deg0 = (r0 < M) ? (float)(g_cnt[r0] + 1) : 0.f;
    float deg1 = (r1 < M) ? (float)(g_cnt[r1] + 1) : 0.f;
    int n0 = nt0 * 8 + 2 * tig;

    float w0 = g_c[n0],      w1 = g_c[n0 + 1];
    float w2 = g_c[n0 + 8],  w3 = g_c[n0 + 9];
    float w4 = g_c[n0 + 16], w5 = g_c[n0 + 17];
    float w6 = g_c[n0 + 24], w7 = g_c[n0 + 25];

    c00 += deg0 * w0; c01 += deg0 * w1; c10 += deg0 * w2; c11 += deg0 * w3;
    c20 += deg0 * w4; c21 += deg0 * w5; c30 += deg0 * w6; c31 += deg0 * w7;
    c02 += deg1 * w0; c03 += deg1 * w1; c12 += deg1 * w2; c13 += deg1 * w3;
    c22 += deg1 * w4; c23 += deg1 * w5; c32 += deg1 * w6; c33 += deg1 * w7;

    if (LSM) {
        float m0v = fmaxf(fmaxf(fmaxf(c00, c01), fmaxf(c10, c11)),
                          fmaxf(fmaxf(c20, c21), fmaxf(c30, c31)));
        float m1v = fmaxf(fmaxf(fmaxf(c02, c03), fmaxf(c12, c13)),
                          fmaxf(fmaxf(c22, c23), fmaxf(c32, c33)));
        m0v = fmaxf(m0v, __shfl_xor_sync(0xFFFFFFFFu, m0v, 1));
        m0v = fmaxf(m0v, __shfl_xor_sync(0xFFFFFFFFu, m0v, 2));
        m1v = fmaxf(m1v, __shfl_xor_sync(0xFFFFFFFFu, m1v, 1));
        m1v = fmaxf(m1v, __shfl_xor_sync(0xFFFFFFFFu, m1v, 2));
        if (tig == 0) { sredm[row0][nq] = m0v; sredm[row1][nq] = m1v; }
        __syncthreads();
        float rm0 = fmaxf(fmaxf(sredm[row0][0], sredm[row0][1]),
                          fmaxf(sredm[row0][2], sredm[row0][3]));
        float rm1 = fmaxf(fmaxf(sredm[row1][0], sredm[row1][1]),
                          fmaxf(sredm[row1][2], sredm[row1][3]));
        float s0 = __expf(c00 - rm0) + __expf(c01 - rm0) + __expf(c10 - rm0) +
                   __expf(c11 - rm0) + __expf(c20 - rm0) + __expf(c21 - rm0) +
                   __expf(c30 - rm0) + __expf(c31 - rm0);
        float s1 = __expf(c02 - rm1) + __expf(c03 - rm1) + __expf(c12 - rm1) +
                   __expf(c13 - rm1) + __expf(c22 - rm1) + __expf(c23 - rm1) +
                   __expf(c32 - rm1) + __expf(c33 - rm1);
        s0 += __shfl_xor_sync(0xFFFFFFFFu, s0, 1);
        s0 += __shfl_xor_sync(0xFFFFFFFFu, s0, 2);
        s1 += __shfl_xor_sync(0xFFFFFFFFu, s1, 1);
        s1 += __shfl_xor_sync(0xFFFFFFFFu, s1, 2);
        if (tig == 0) { sreds[row0][nq] = s0; sreds[row1][nq] = s1; }
        __syncthreads();
        float t0 = (sreds[row0][0] + sreds[row0][1]) + (sreds[row0][2] + sreds[row0][3]);
        float t1 = (sreds[row1][0] + sreds[row1][1]) + (sreds[row1][2] + sreds[row1][3]);
        float l0 = rm0 + __logf(t0);
        float l1 = rm1 + __logf(t1);
        c00 -= l0; c01 -= l0; c10 -= l0; c11 -= l0;
        c20 -= l0; c21 -= l0; c30 -= l0; c31 -= l0;
        c02 -= l1; c03 -= l1; c12 -= l1; c13 -= l1;
        c22 -= l1; c23 -= l1; c32 -= l1; c33 -= l1;
    }

    if (FIRST) {
        // write h1 as packed fp16 into g_hh
        if (r0 < M) {
            size_t b = ((size_t)r0 * F + n0) >> 1;
            g_hh[b]      = h2u(__floats2half2_rn(c00, c01));
            g_hh[b + 4]  = h2u(__floats2half2_rn(c10, c11));
            g_hh[b + 8]  = h2u(__floats2half2_rn(c20, c21));
            g_hh[b + 12] = h2u(__floats2half2_rn(c30, c31));
        }
        if (r1 < M) {
            size_t b = ((size_t)r1 * F + n0) >> 1;
            g_hh[b]      = h2u(__floats2half2_rn(c02, c03));
            g_hh[b + 4]  = h2u(__floats2half2_rn(c12, c13));
            g_hh[b + 8]  = h2u(__floats2half2_rn(c22, c23));
            g_hh[b + 12] = h2u(__floats2half2_rn(c32, c33));
        }
    } else {
        float* dp = dst_param;
        if (r0 < M) {
            *(float2*)&dp[(size_t)r0 * F + n0]      = make_float2(c00, c01);
            *(float2*)&dp[(size_t)r0 * F + n0 + 8]  = make_float2(c10, c11);
            *(float2*)&dp[(size_t)r0 * F + n0 + 16] = make_float2(c20, c21);
            *(float2*)&dp[(size_t)r0 * F + n0 + 24] = make_float2(c30, c31);
        }
        if (r1 < M) {
            *(float2*)&dp[(size_t)r1 * F + n0]      = make_float2(c02, c03);
            *(float2*)&dp[(size_t)r1 * F + n0 + 8]  = make_float2(c12, c13);
            *(float2*)&dp[(size_t)r1 * F + n0 + 16] = make_float2(c22, c23);
            *(float2*)&dp[(size_t)r1 * F + n0 + 24] = make_float2(c32, c33);
        }
    }
}

// ---------------- launch ----------------
extern "C" void kernel_launch(void* const* d_in, const int* in_sizes, int n_in,
                              void* d_out, int out_size) {
    const float* x  = (const float*)d_in[0];
    const void*  ei = d_in[1];
    const float* w1 = (const float*)d_in[2];
    const float* b1 = (const float*)d_in[3];
    const float* w2 = (const float*)d_in[4];
    const float* b2 = (const float*)d_in[5];
    float* out = (float*)d_out;

    int n = in_sizes[0] / F;     // 50000
    int e = in_sizes[1] / 2;     // 600000
    int nb = (n + 511) / 512;    // scan blocks (98)

    // detect dtype + zero histogram + convert x -> fp16 (one launch)
    k_init<<<(n + 255) / 256 + 1, 256>>>((const unsigned int*)ei, (const float4*)x, n);

    // fold layers straight into tf32 fragments + fold bias (one launch)
    k_prep_wcf<<<F + 1, F>>>(w1, w2, b1, b2);

    // CSR by dst (counting sort, 2-phase scan)
    k_hist<<<(e + 255) / 256, 256>>>(ei, e, n);
    k_scan_block<<<nb, 512>>>(n);
    k_scan_add<<<nb, 512>>>(n, nb);
    k_fill<<<(e + 255) / 256, 256>>>(ei, e, n);

    int conv_blocks = (n + GBM - 1) / GBM;

    // conv1: g_hh = fp16(conv(x))    conv2+lsm: out = log_softmax(conv(g_hh))
    k_conv<true,  false><<<conv_blocks, 256>>>(nullptr, n);
    k_conv<false, true ><<<conv_blocks, 256>>>(out, n);
}

// round 14
// speedup vs baseline: 1.7647x; 1.0292x over previous
#include <cuda_runtime.h>
#include <cuda_fp16.h>
#include <stdint.h>
#include <string.h>

#define NN 50000
#define NE 600000
#define F  128
#define GBM 32
#define CSRB 98          // csr blocks (co-resident: <= SM count)

// ---------------- scratch (static device globals: no allocations) ----------
__device__ __align__(16) uint32_t g_Wf[16 * 16 * 32 * 2];// W = W1^T W2^T, tf32 B-fragment order
__device__ __align__(16) float    g_c[F];                // combined bias c = b1 W2^T + b2
__device__ int   g_cnt[NN];                              // in-degree histogram (real edges)
__device__ int   g_rowstart[NN + 1];                     // CSR row offsets (by dst)
__device__ int   g_cursor[NN];                           // fill cursors
__device__ int   g_bsum[128];                            // per-block scan sums
__device__ int   g_sorted[NE];                           // src indices sorted by dst
__device__ __align__(16) uint32_t g_xh[(size_t)NN * F / 2]; // x in fp16 (packed half2)
__device__ __align__(16) uint32_t g_hh[(size_t)NN * F / 2]; // h1 in fp16 (packed half2)
__device__ int   d_is64;                                 // 1 if edge_index is int64
__device__ int   g_bar1, g_bar2, g_bar3;                 // csr spin barriers

__device__ __forceinline__ uint32_t f2tf(float f) {
    uint32_t u;
    asm("cvt.rna.tf32.f32 %0, %1;" : "=r"(u) : "f"(f));
    return u;
}

__device__ __forceinline__ uint32_t h2u(__half2 h) {
    uint32_t u;
    memcpy(&u, &h, 4);
    return u;
}

// 32-bit index load: for int64 (little-endian, values < 2^31) read the low word.
__device__ __forceinline__ int load_idx(const void* ei, int e, int row, int i) {
    const int* p = (const int*)ei;
    if (d_is64) return p[2 * ((size_t)row * e + i)];
    return p[row * e + i];
}

// ---------------- launch 0: detect + zero + x->fp16 + weight fold -----------
// b==0            : int64 detect + zero spin barriers
// b in [1,196]    : zero g_cnt; grid-stride convert x -> fp16
// b in [197,261]  : fold W (k = (b-197)*2 + t/128) into tf32 fragments; k==128 -> bias
__global__ __launch_bounds__(256) void k_init_all(
    const unsigned int* __restrict__ w, const float4* __restrict__ x4,
    const float* __restrict__ w1, const float* __restrict__ w2,
    const float* __restrict__ b1, const float* __restrict__ b2, int n) {
    int b = blockIdx.x, t = threadIdx.x;
    if (b == 0) {
        __shared__ int nz;
        if (t == 0) { nz = 0; g_bar1 = 0; g_bar2 = 0; g_bar3 = 0; }
        __syncthreads();
        int local = 0;
        for (int i = t; i < 2048; i += blockDim.x)
            if (w[2 * i + 1] != 0u) local = 1;
        if (local) atomicOr(&nz, 1);
        __syncthreads();
        if (t == 0) d_is64 = (nz == 0) ? 1 : 0;
        return;
    }
    if (b <= 196) {
        int i = (b - 1) * 256 + t;
        if (i < n) g_cnt[i] = 0;
        int total = n * (F / 8);
        int stride = 196 * 256;
        for (int idx = i; idx < total; idx += stride) {
            float4 v0 = x4[idx * 2];
            float4 v1 = x4[idx * 2 + 1];
            uint4 o;
            o.x = h2u(__floats2half2_rn(v0.x, v0.y));
            o.y = h2u(__floats2half2_rn(v0.z, v0.w));
            o.z = h2u(__floats2half2_rn(v1.x, v1.y));
            o.w = h2u(__floats2half2_rn(v1.z, v1.w));
            ((uint4*)g_xh)[idx] = o;
        }
        return;
    }
    // weight fold: k in [0,128]; k==F -> bias
    int k = (b - 197) * 2 + (t >> 7);
    int i = t & 127;
    if (k > F) return;
    if (k == F) {
        float s = b2[i];
#pragma unroll 4
        for (int j = 0; j < F; j++) s += b1[j] * w2[i * F + j];
        g_c[i] = s;
        return;
    }
    float s = 0.f;
#pragma unroll 4
    for (int j = 0; j < F; j++) s += w1[j * F + k] * w2[i * F + j];
    int idx = ((k >> 3) * 512 + (i >> 3) * 32 + (i & 7) * 4 + (k & 3)) * 2 + ((k >> 2) & 1);
    g_Wf[idx] = f2tf(s);
}

// ---------------- launch 1: fused CSR (hist -> scan -> offsets -> fill) -----
// 98 co-resident blocks; spin barriers between phases (counters zeroed in init).
__device__ __forceinline__ void grid_bar(int* ctr, int nb) {
    __syncthreads();
    if (threadIdx.x == 0) {
        __threadfence();
        atomicAdd(ctr, 1);
        while (atomicAdd(ctr, 0) < nb) { }
    }
    __syncthreads();
}

__global__ __launch_bounds__(512) void k_csr(const void* __restrict__ ei, int e, int n) {
    __shared__ int wsum[16];
    __shared__ int off_s;
    int t = threadIdx.x, b = blockIdx.x;
    int nb = gridDim.x;
    int nt = nb * 512;
    int lane = t & 31, w = t >> 5;

    // phase 0: histogram
    for (int i = b * 512 + t; i < e; i += nt) {
        int dst = load_idx(ei, e, 1, i);
        if ((unsigned)dst < (unsigned)n) atomicAdd(&g_cnt[dst], 1);
    }
    grid_bar(&g_bar1, nb);

    // phase 1: per-block exclusive scan (one element/thread)
    int gidx = b * 512 + t;
    int v = (gidx < n) ? g_cnt[gidx] : 0;
    int x = v;
#pragma unroll
    for (int o = 1; o < 32; o <<= 1) {
        int y = __shfl_up_sync(0xFFFFFFFFu, x, o);
        if (lane >= o) x += y;
    }
    if (lane == 31) wsum[w] = x;
    __syncthreads();
    if (w == 0 && lane < 16) {
        int s = wsum[lane];
#pragma unroll
        for (int o = 1; o < 16; o <<= 1) {
            int y = __shfl_up_sync(0xFFFFu, s, o);
            if (lane >= o) s += y;
        }
        wsum[lane] = s;
    }
    __syncthreads();
    int incl = x + (w > 0 ? wsum[w - 1] : 0);
    if (gidx < n) g_rowstart[gidx] = incl - v;
    if (t == 511) g_bsum[b] = incl;
    grid_bar(&g_bar2, nb);

    // phase 2: block offsets + cursors (+ grand total by block 0)
    if (t < 32) {
        int acc = 0, tot = 0;
        for (int j = t; j < nb; j += 32) {
            int vv = g_bsum[j];
            tot += vv;
            if (j < b) acc += vv;
        }
#pragma unroll
        for (int o = 16; o; o >>= 1) {
            acc += __shfl_xor_sync(0xFFFFFFFFu, acc, o);
            tot += __shfl_xor_sync(0xFFFFFFFFu, tot, o);
        }
        if (t == 0) {
            off_s = acc;
            if (b == 0) g_rowstart[n] = tot;
        }
    }
    __syncthreads();
    if (gidx < n) {
        int vv = g_rowstart[gidx] + off_s;
        g_rowstart[gidx] = vv;
        g_cursor[gidx]   = vv;
    }
    grid_bar(&g_bar3, nb);

    // phase 3: fill
    for (int i = b * 512 + t; i < e; i += nt) {
        int src = load_idx(ei, e, 0, i);
        int dst = load_idx(ei, e, 1, i);
        if ((unsigned)src < (unsigned)n && (unsigned)dst < (unsigned)n) {
            int p = atomicAdd(&g_cursor[dst], 1);
            g_sorted[p] = src;
        }
    }
}

// ---------------- fused conv: fp16 gather-agg + TF32 MMA + epilogue ---------
#define MMA_TF32(c0, c1, c2, c3, bx, by)                                      \
    asm volatile(                                                             \
        "mma.sync.aligned.m16n8k8.row.col.f32.tf32.tf32.f32 "                 \
        "{%0,%1,%2,%3}, {%4,%5,%6,%7}, {%8,%9}, {%0,%1,%2,%3};"               \
        : "+f"(c0), "+f"(c1), "+f"(c2), "+f"(c3)                              \
        : "r"(a0), "r"(a1), "r"(a2), "r"(a3), "r"(bx), "r"(by))

template <bool FIRST, bool LSM>
__global__ __launch_bounds__(256) void k_conv(float* __restrict__ dst_param, int M) {
    __shared__ uint32_t As[GBM * 132];
    __shared__ float sredm[GBM][4];
    __shared__ float sreds[GBM][4];
    int tid = threadIdx.x;
    int warp = tid >> 5, lane = tid & 31;
    int gid = lane >> 2, tig = lane & 3;
    int m0 = blockIdx.x * GBM;

    const uint2* hv = FIRST ? (const uint2*)g_xh : (const uint2*)g_hh;

#pragma unroll
    for (int r = 0; r < 4; r++) {
        int row = warp * 4 + r;
        int gm  = m0 + row;
        float ax = 0.f, ay = 0.f, az = 0.f, aw = 0.f;
        if (gm < M) {
            uint2 u = hv[(size_t)gm * 32 + lane];     // self loop
            float2 p0 = __half22float2(*(__half2*)&u.x);
            float2 p1 = __half22float2(*(__half2*)&u.y);
            ax = p0.x; ay = p0.y; az = p1.x; aw = p1.y;
            int s = g_rowstart[gm], e2 = g_rowstart[gm + 1];
            int i = s;
            for (; i + 3 < e2; i += 4) {              // MLP=4
                int s0 = g_sorted[i],     s1 = g_sorted[i + 1];
                int s2 = g_sorted[i + 2], s3 = g_sorted[i + 3];
                uint2 u0 = hv[(size_t)s0 * 32 + lane];
                uint2 u1 = hv[(size_t)s1 * 32 + lane];
                uint2 u2 = hv[(size_t)s2 * 32 + lane];
                uint2 u3 = hv[(size_t)s3 * 32 + lane];
                float2 q;
                q = __half22float2(*(__half2*)&u0.x); ax += q.x; ay += q.y;
                q = __half22float2(*(__half2*)&u0.y); az += q.x; aw += q.y;
                q = __half22float2(*(__half2*)&u1.x); ax += q.x; ay += q.y;
                q = __half22float2(*(__half2*)&u1.y); az += q.x; aw += q.y;
                q = __half22float2(*(__half2*)&u2.x); ax += q.x; ay += q.y;
                q = __half22float2(*(__half2*)&u2.y); az += q.x; aw += q.y;
                q = __half22float2(*(__half2*)&u3.x); ax += q.x; ay += q.y;
                q = __half22float2(*(__half2*)&u3.y); az += q.x; aw += q.y;
            }
            for (; i < e2; i++) {
                uint2 u4 = hv[(size_t)g_sorted[i] * 32 + lane];
                float2 q;
                q = __half22float2(*(__half2*)&u4.x); ax += q.x; ay += q.y;
                q = __half22float2(*(__half2*)&u4.y); az += q.x; aw += q.y;
            }
        }
        uint4 t;
        t.x = f2tf(ax); t.y = f2tf(ay); t.z = f2tf(az); t.w = f2tf(aw);
        *(uint4*)&As[row * 132 + lane * 4] = t;
    }
    __syncthreads();

    int mrow0 = (warp & 1) * 16;
    int nq    = warp >> 1;
    int nt0   = nq * 4;

    float c00 = 0.f, c01 = 0.f, c02 = 0.f, c03 = 0.f;
    float c10 = 0.f, c11 = 0.f, c12 = 0.f, c13 = 0.f;
    float c20 = 0.f, c21 = 0.f, c22 = 0.f, c23 = 0.f;
    float c30 = 0.f, c31 = 0.f, c32 = 0.f, c33 = 0.f;

    int abase = (mrow0 + gid) * 132;
    for (int kc = 0; kc < 16; kc++) {
        uint32_t a0 = As[abase + kc * 8 + tig];
        uint32_t a1 = As[abase + 8 * 132 + kc * 8 + tig];
        uint32_t a2 = As[abase + kc * 8 + tig + 4];
        uint32_t a3 = As[abase + 8 * 132 + kc * 8 + tig + 4];
        const uint2* wf = (const uint2*)g_Wf + (size_t)kc * 512 + nt0 * 32 + lane;
        uint2 b0 = wf[0];
        uint2 b1 = wf[32];
        uint2 b2 = wf[64];
        uint2 b3 = wf[96];
        MMA_TF32(c00, c01, c02, c03, b0.x, b0.y);
        MMA_TF32(c10, c11, c12, c13, b1.x, b1.y);
        MMA_TF32(c20, c21, c22, c23, b2.x, b2.y);
        MMA_TF32(c30, c31, c32, c33, b3.x, b3.y);
    }

    int row0 = mrow0 + gid;
    int row1 = row0 + 8;
    int r0 = m0 + row0;
    int r1 = m0 + row1;
    float deg0 = (r0 < M) ? (float)(g_cnt[r0] + 1) : 0.f;
    float deg1 = (r1 < M) ? (float)(g_cnt[r1] + 1) : 0.f;
    int n0 = nt0 * 8 + 2 * tig;

    float w0 = g_c[n0],      w1 = g_c[n0 + 1];
    float w2 = g_c[n0 + 8],  w3 = g_c[n0 + 9];
    float w4 = g_c[n0 + 16], w5 = g_c[n0 + 17];
    float w6 = g_c[n0 + 24], w7 = g_c[n0 + 25];

    c00 += deg0 * w0; c01 += deg0 * w1; c10 += deg0 * w2; c11 += deg0 * w3;
    c20 += deg0 * w4; c21 += deg0 * w5; c30 += deg0 * w6; c31 += deg0 * w7;
    c02 += deg1 * w0; c03 += deg1 * w1; c12 += deg1 * w2; c13 += deg1 * w3;
    c22 += deg1 * w4; c23 += deg1 * w5; c32 += deg1 * w6; c33 += deg1 * w7;

    if (LSM) {
        float m0v = fmaxf(fmaxf(fmaxf(c00, c01), fmaxf(c10, c11)),
                          fmaxf(fmaxf(c20, c21), fmaxf(c30, c31)));
        float m1v = fmaxf(fmaxf(fmaxf(c02, c03), fmaxf(c12, c13)),
                          fmaxf(fmaxf(c22, c23), fmaxf(c32, c33)));
        m0v = fmaxf(m0v, __shfl_xor_sync(0xFFFFFFFFu, m0v, 1));
        m0v = fmaxf(m0v, __shfl_xor_sync(0xFFFFFFFFu, m0v, 2));
        m1v = fmaxf(m1v, __shfl_xor_sync(0xFFFFFFFFu, m1v, 1));
        m1v = fmaxf(m1v, __shfl_xor_sync(0xFFFFFFFFu, m1v, 2));
        if (tig == 0) { sredm[row0][nq] = m0v; sredm[row1][nq] = m1v; }
        __syncthreads();
        float rm0 = fmaxf(fmaxf(sredm[row0][0], sredm[row0][1]),
                          fmaxf(sredm[row0][2], sredm[row0][3]));
        float rm1 = fmaxf(fmaxf(sredm[row1][0], sredm[row1][1]),
                          fmaxf(sredm[row1][2], sredm[row1][3]));
        float s0 = __expf(c00 - rm0) + __expf(c01 - rm0) + __expf(c10 - rm0) +
                   __expf(c11 - rm0) + __expf(c20 - rm0) + __expf(c21 - rm0) +
                   __expf(c30 - rm0) + __expf(c31 - rm0);
        float s1 = __expf(c02 - rm1) + __expf(c03 - rm1) + __expf(c12 - rm1) +
                   __expf(c13 - rm1) + __expf(c22 - rm1) + __expf(c23 - rm1) +
                   __expf(c32 - rm1) + __expf(c33 - rm1);
        s0 += __shfl_xor_sync(0xFFFFFFFFu, s0, 1);
        s0 += __shfl_xor_sync(0xFFFFFFFFu, s0, 2);
        s1 += __shfl_xor_sync(0xFFFFFFFFu, s1, 1);
        s1 += __shfl_xor_sync(0xFFFFFFFFu, s1, 2);
        if (tig == 0) { sreds[row0][nq] = s0; sreds[row1][nq] = s1; }
        __syncthreads();
        float t0 = (sreds[row0][0] + sreds[row0][1]) + (sreds[row0][2] + sreds[row0][3]);
        float t1 = (sreds[row1][0] + sreds[row1][1]) + (sreds[row1][2] + sreds[row1][3]);
        float l0 = rm0 + __logf(t0);
        float l1 = rm1 + __logf(t1);
        c00 -= l0; c01 -= l0; c10 -= l0; c11 -= l0;
        c20 -= l0; c21 -= l0; c30 -= l0; c31 -= l0;
        c02 -= l1; c03 -= l1; c12 -= l1; c13 -= l1;
        c22 -= l1; c23 -= l1; c32 -= l1; c33 -= l1;
    }

    if (FIRST) {
        if (r0 < M) {
            size_t b = ((size_t)r0 * F + n0) >> 1;
            g_hh[b]      = h2u(__floats2half2_rn(c00, c01));
            g_hh[b + 4]  = h2u(__floats2half2_rn(c10, c11));
            g_hh[b + 8]  = h2u(__floats2half2_rn(c20, c21));
            g_hh[b + 12] = h2u(__floats2half2_rn(c30, c31));
        }
        if (r1 < M) {
            size_t b = ((size_t)r1 * F + n0) >> 1;
            g_hh[b]      = h2u(__floats2half2_rn(c02, c03));
            g_hh[b + 4]  = h2u(__floats2half2_rn(c12, c13));
            g_hh[b + 8]  = h2u(__floats2half2_rn(c22, c23));
            g_hh[b + 12] = h2u(__floats2half2_rn(c32, c33));
        }
    } else {
        float* dp = dst_param;
        if (r0 < M) {
            *(float2*)&dp[(size_t)r0 * F + n0]      = make_float2(c00, c01);
            *(float2*)&dp[(size_t)r0 * F + n0 + 8]  = make_float2(c10, c11);
            *(float2*)&dp[(size_t)r0 * F + n0 + 16] = make_float2(c20, c21);
            *(float2*)&dp[(size_t)r0 * F + n0 + 24] = make_float2(c30, c31);
        }
        if (r1 < M) {
            *(float2*)&dp[(size_t)r1 * F + n0]      = make_float2(c02, c03);
            *(float2*)&dp[(size_t)r1 * F + n0 + 8]  = make_float2(c12, c13);
            *(float2*)&dp[(size_t)r1 * F + n0 + 16] = make_float2(c22, c23);
            *(float2*)&dp[(size_t)r1 * F + n0 + 24] = make_float2(c32, c33);
        }
    }
}

// ---------------- launch ----------------
extern "C" void kernel_launch(void* const* d_in, const int* in_sizes, int n_in,
                              void* d_out, int out_size) {
    const float* x  = (const float*)d_in[0];
    const void*  ei = d_in[1];
    const float* w1 = (const float*)d_in[2];
    const float* b1 = (const float*)d_in[3];
    const float* w2 = (const float*)d_in[4];
    const float* b2 = (const float*)d_in[5];
    float* out = (float*)d_out;

    int n = in_sizes[0] / F;     // 50000
    int e = in_sizes[1] / 2;     // 600000

    // launch 0: detect + zero + x->fp16 + weight fold
    k_init_all<<<262, 256>>>((const unsigned int*)ei, (const float4*)x,
                             w1, w2, b1, b2, n);
    // launch 1: fused CSR (hist/scan/offsets/fill with co-resident spin barriers)
    k_csr<<<CSRB, 512>>>(ei, e, n);

    int conv_blocks = (n + GBM - 1) / GBM;
    // launch 2: conv1       launch 3 (PROFILED): conv2 + log_softmax
    k_conv<true,  false><<<conv_blocks, 256>>>(nullptr, n);
    k_conv<false, true ><<<conv_blocks, 256>>>(out, n);
}

// round 16
// speedup vs baseline: 1.7910x; 1.0149x over previous
#include <cuda_runtime.h>
#include <cuda_fp16.h>
#include <stdint.h>
#include <string.h>

#define NN 50000
#define NE 600000
#define F  128
#define GBM 32
#define CSRB 98          // csr blocks (co-resident: <= SM count)

// ---------------- scratch (static device globals: no allocations) ----------
__device__ __align__(16) uint32_t g_Wf[16 * 16 * 32 * 2];// W = W1^T W2^T, tf32 B-fragment order
__device__ __align__(16) float    g_c[F];                // combined bias c = b1 W2^T + b2
__device__ int   g_cnt[NN];                              // in-degree histogram (real edges)
__device__ int   g_rowstart[NN + 1];                     // CSR row offsets (by dst)
__device__ int   g_cursor[NN];                           // fill cursors
__device__ int   g_bsum[128];                            // per-block scan sums
__device__ int   g_sorted[NE];                           // src indices sorted by dst
__device__ __align__(16) uint32_t g_xh[(size_t)NN * F / 2]; // x in fp16 (packed half2)
__device__ __align__(16) uint32_t g_hh[(size_t)NN * F / 2]; // h1 in fp16 (packed half2)
__device__ int   d_is64;                                 // 1 if edge_index is int64
__device__ int   g_bar1, g_bar2, g_bar3;                 // csr spin barriers

__device__ __forceinline__ uint32_t f2tf(float f) {
    uint32_t u;
    asm("cvt.rna.tf32.f32 %0, %1;" : "=r"(u) : "f"(f));
    return u;
}

__device__ __forceinline__ uint32_t h2u(__half2 h) {
    uint32_t u;
    memcpy(&u, &h, 4);
    return u;
}

__device__ __forceinline__ __half2 u2h(uint32_t u) {
    __half2 h;
    memcpy(&h, &u, 4);
    return h;
}

// 32-bit index load: for int64 (little-endian, values < 2^31) read the low word.
__device__ __forceinline__ int load_idx(const void* ei, int e, int row, int i) {
    const int* p = (const int*)ei;
    if (d_is64) return p[2 * ((size_t)row * e + i)];
    return p[row * e + i];
}

// ---------------- launch 0: detect + zero + x->fp16 + weight fold -----------
__global__ __launch_bounds__(256) void k_init_all(
    const unsigned int* __restrict__ w, const float4* __restrict__ x4,
    const float* __restrict__ w1, const float* __restrict__ w2,
    const float* __restrict__ b1, const float* __restrict__ b2, int n) {
    int b = blockIdx.x, t = threadIdx.x;
    if (b == 0) {
        __shared__ int nz;
        if (t == 0) { nz = 0; g_bar1 = 0; g_bar2 = 0; g_bar3 = 0; }
        __syncthreads();
        int local = 0;
        for (int i = t; i < 2048; i += blockDim.x)
            if (w[2 * i + 1] != 0u) local = 1;
        if (local) atomicOr(&nz, 1);
        __syncthreads();
        if (t == 0) d_is64 = (nz == 0) ? 1 : 0;
        return;
    }
    if (b <= 196) {
        int i = (b - 1) * 256 + t;
        if (i < n) g_cnt[i] = 0;
        int total = n * (F / 8);
        int stride = 196 * 256;
        for (int idx = i; idx < total; idx += stride) {
            float4 v0 = x4[idx * 2];
            float4 v1 = x4[idx * 2 + 1];
            uint4 o;
            o.x = h2u(__floats2half2_rn(v0.x, v0.y));
            o.y = h2u(__floats2half2_rn(v0.z, v0.w));
            o.z = h2u(__floats2half2_rn(v1.x, v1.y));
            o.w = h2u(__floats2half2_rn(v1.z, v1.w));
            ((uint4*)g_xh)[idx] = o;
        }
        return;
    }
    int k = (b - 197) * 2 + (t >> 7);
    int i = t & 127;
    if (k > F) return;
    if (k == F) {
        float s = b2[i];
#pragma unroll 4
        for (int j = 0; j < F; j++) s += b1[j] * w2[i * F + j];
        g_c[i] = s;
        return;
    }
    float s = 0.f;
#pragma unroll 4
    for (int j = 0; j < F; j++) s += w1[j * F + k] * w2[i * F + j];
    int idx = ((k >> 3) * 512 + (i >> 3) * 32 + (i & 7) * 4 + (k & 3)) * 2 + ((k >> 2) & 1);
    g_Wf[idx] = f2tf(s);
}

// ---------------- launch 1: fused CSR (hist -> scan -> offsets -> fill) -----
__device__ __forceinline__ void grid_bar(int* ctr, int nb) {
    __syncthreads();
    if (threadIdx.x == 0) {
        __threadfence();
        atomicAdd(ctr, 1);
        while (atomicAdd(ctr, 0) < nb) { }
    }
    __syncthreads();
}

__global__ __launch_bounds__(512) void k_csr(const void* __restrict__ ei, int e, int n) {
    __shared__ int wsum[16];
    __shared__ int off_s;
    int t = threadIdx.x, b = blockIdx.x;
    int nb = gridDim.x;
    int nt = nb * 512;
    int lane = t & 31, w = t >> 5;

    for (int i = b * 512 + t; i < e; i += nt) {
        int dst = load_idx(ei, e, 1, i);
        if ((unsigned)dst < (unsigned)n) atomicAdd(&g_cnt[dst], 1);
    }
    grid_bar(&g_bar1, nb);

    int gidx = b * 512 + t;
    int v = (gidx < n) ? g_cnt[gidx] : 0;
    int x = v;
#pragma unroll
    for (int o = 1; o < 32; o <<= 1) {
        int y = __shfl_up_sync(0xFFFFFFFFu, x, o);
        if (lane >= o) x += y;
    }
    if (lane == 31) wsum[w] = x;
    __syncthreads();
    if (w == 0 && lane < 16) {
        int s = wsum[lane];
#pragma unroll
        for (int o = 1; o < 16; o <<= 1) {
            int y = __shfl_up_sync(0xFFFFu, s, o);
            if (lane >= o) s += y;
        }
        wsum[lane] = s;
    }
    __syncthreads();
    int incl = x + (w > 0 ? wsum[w - 1] : 0);
    if (gidx < n) g_rowstart[gidx] = incl - v;
    if (t == 511) g_bsum[b] = incl;
    grid_bar(&g_bar2, nb);

    if (t < 32) {
        int acc = 0, tot = 0;
        for (int j = t; j < nb; j += 32) {
            int vv = g_bsum[j];
            tot += vv;
            if (j < b) acc += vv;
        }
#pragma unroll
        for (int o = 16; o; o >>= 1) {
            acc += __shfl_xor_sync(0xFFFFFFFFu, acc, o);
            tot += __shfl_xor_sync(0xFFFFFFFFu, tot, o);
        }
        if (t == 0) {
            off_s = acc;
            if (b == 0) g_rowstart[n] = tot;
        }
    }
    __syncthreads();
    if (gidx < n) {
        int vv = g_rowstart[gidx] + off_s;
        g_rowstart[gidx] = vv;
        g_cursor[gidx]   = vv;
    }
    grid_bar(&g_bar3, nb);

    for (int i = b * 512 + t; i < e; i += nt) {
        int src = load_idx(ei, e, 0, i);
        int dst = load_idx(ei, e, 1, i);
        if ((unsigned)src < (unsigned)n && (unsigned)dst < (unsigned)n) {
            int p = atomicAdd(&g_cursor[dst], 1);
            g_sorted[p] = src;
        }
    }
}

// ---------------- fused conv: fp16 gather (HADD2 trees) + TF32 MMA ----------
#define MMA_TF32(c0, c1, c2, c3, bx, by)                                      \
    asm volatile(                                                             \
        "mma.sync.aligned.m16n8k8.row.col.f32.tf32.tf32.f32 "                 \
        "{%0,%1,%2,%3}, {%4,%5,%6,%7}, {%8,%9}, {%0,%1,%2,%3};"               \
        : "+f"(c0), "+f"(c1), "+f"(c2), "+f"(c3)                              \
        : "r"(a0), "r"(a1), "r"(a2), "r"(a3), "r"(bx), "r"(by))

template <bool FIRST, bool LSM>
__global__ __launch_bounds__(256) void k_conv(float* __restrict__ dst_param, int M) {
    __shared__ uint32_t As[GBM * 132];
    __shared__ float sredm[GBM][4];
    __shared__ float sreds[GBM][4];
    int tid = threadIdx.x;
    int warp = tid >> 5, lane = tid & 31;
    int gid = lane >> 2, tig = lane & 3;
    int m0 = blockIdx.x * GBM;

    const uint2* hv = FIRST ? (const uint2*)g_xh : (const uint2*)g_hh;

    // ---- aggregation: warp handles rows [warp*4, warp*4+4), lane = 8B chunk.
    // Gathered half2 values are tree-summed in fp16 per 8/4-group (HADD2),
    // promoted once per group into the fp32 accumulator.
#pragma unroll
    for (int r = 0; r < 4; r++) {
        int row = warp * 4 + r;
        int gm  = m0 + row;
        float ax = 0.f, ay = 0.f, az = 0.f, aw = 0.f;
        if (gm < M) {
            uint2 u = hv[(size_t)gm * 32 + lane];     // self loop
            float2 p0 = __half22float2(u2h(u.x));
            float2 p1 = __half22float2(u2h(u.y));
            ax = p0.x; ay = p0.y; az = p1.x; aw = p1.y;
            int s = g_rowstart[gm], e2 = g_rowstart[gm + 1];
            int i = s;
            for (; i + 7 < e2; i += 8) {              // MLP=8, fp16 tree sum
                int s0 = g_sorted[i],     s1 = g_sorted[i + 1];
                int s2 = g_sorted[i + 2], s3 = g_sorted[i + 3];
                int s4 = g_sorted[i + 4], s5 = g_sorted[i + 5];
                int s6 = g_sorted[i + 6], s7 = g_sorted[i + 7];
                uint2 u0 = hv[(size_t)s0 * 32 + lane];
                uint2 u1 = hv[(size_t)s1 * 32 + lane];
                uint2 u2 = hv[(size_t)s2 * 32 + lane];
                uint2 u3 = hv[(size_t)s3 * 32 + lane];
                uint2 u4 = hv[(size_t)s4 * 32 + lane];
                uint2 u5 = hv[(size_t)s5 * 32 + lane];
                uint2 u6 = hv[(size_t)s6 * 32 + lane];
                uint2 u7 = hv[(size_t)s7 * 32 + lane];
                __half2 hx = __hadd2(
                    __hadd2(__hadd2(u2h(u0.x), u2h(u1.x)), __hadd2(u2h(u2.x), u2h(u3.x))),
                    __hadd2(__hadd2(u2h(u4.x), u2h(u5.x)), __hadd2(u2h(u6.x), u2h(u7.x))));
                __half2 hy = __hadd2(
                    __hadd2(__hadd2(u2h(u0.y), u2h(u1.y)), __hadd2(u2h(u2.y), u2h(u3.y))),
                    __hadd2(__hadd2(u2h(u4.y), u2h(u5.y)), __hadd2(u2h(u6.y), u2h(u7.y))));
                float2 q0 = __half22float2(hx);
                float2 q1 = __half22float2(hy);
                ax += q0.x; ay += q0.y; az += q1.x; aw += q1.y;
            }
            if (i + 3 < e2) {                         // 4-group
                int s0 = g_sorted[i],     s1 = g_sorted[i + 1];
                int s2 = g_sorted[i + 2], s3 = g_sorted[i + 3];
                uint2 u0 = hv[(size_t)s0 * 32 + lane];
                uint2 u1 = hv[(size_t)s1 * 32 + lane];
                uint2 u2 = hv[(size_t)s2 * 32 + lane];
                uint2 u3 = hv[(size_t)s3 * 32 + lane];
                __half2 hx = __hadd2(__hadd2(u2h(u0.x), u2h(u1.x)),
                                     __hadd2(u2h(u2.x), u2h(u3.x)));
                __half2 hy = __hadd2(__hadd2(u2h(u0.y), u2h(u1.y)),
                                     __hadd2(u2h(u2.y), u2h(u3.y)));
                float2 q0 = __half22float2(hx);
                float2 q1 = __half22float2(hy);
                ax += q0.x; ay += q0.y; az += q1.x; aw += q1.y;
                i += 4;
            }
            for (; i < e2; i++) {                     // scalar tail (fp32 adds)
                uint2 u4 = hv[(size_t)g_sorted[i] * 32 + lane];
                float2 q;
                q = __half22float2(u2h(u4.x)); ax += q.x; ay += q.y;
                q = __half22float2(u2h(u4.y)); az += q.x; aw += q.y;
            }
        }
        uint4 t;
        t.x = f2tf(ax); t.y = f2tf(ay); t.z = f2tf(az); t.w = f2tf(aw);
        *(uint4*)&As[row * 132 + lane * 4] = t;
    }
    __syncthreads();

    int mrow0 = (warp & 1) * 16;
    int nq    = warp >> 1;
    int nt0   = nq * 4;

    float c00 = 0.f, c01 = 0.f, c02 = 0.f, c03 = 0.f;
    float c10 = 0.f, c11 = 0.f, c12 = 0.f, c13 = 0.f;
    float c20 = 0.f, c21 = 0.f, c22 = 0.f, c23 = 0.f;
    float c30 = 0.f, c31 = 0.f, c32 = 0.f, c33 = 0.f;

    int abase = (mrow0 + gid) * 132;
    for (int kc = 0; kc < 16; kc++) {
        uint32_t a0 = As[abase + kc * 8 + tig];
        uint32_t a1 = As[abase + 8 * 132 + kc * 8 + tig];
        uint32_t a2 = As[abase + kc * 8 + tig + 4];
        uint32_t a3 = As[abase + 8 * 132 + kc * 8 + tig + 4];
        const uint2* wf = (const uint2*)g_Wf + (size_t)kc * 512 + nt0 * 32 + lane;
        uint2 b0 = wf[0];
        uint2 b1 = wf[32];
        uint2 b2 = wf[64];
        uint2 b3 = wf[96];
        MMA_TF32(c00, c01, c02, c03, b0.x, b0.y);
        MMA_TF32(c10, c11, c12, c13, b1.x, b1.y);
        MMA_TF32(c20, c21, c22, c23, b2.x, b2.y);
        MMA_TF32(c30, c31, c32, c33, b3.x, b3.y);
    }

    int row0 = mrow0 + gid;
    int row1 = row0 + 8;
    int r0 = m0 + row0;
    int r1 = m0 + row1;
    float deg0 = (r0 < M) ? (float)(g_cnt[r0] + 1) : 0.f;
    float deg1 = (r1 < M) ? (float)(g_cnt[r1] + 1) : 0.f;
    int n0 = nt0 * 8 + 2 * tig;

    float w0 = g_c[n0],      w1 = g_c[n0 + 1];
    float w2 = g_c[n0 + 8],  w3 = g_c[n0 + 9];
    float w4 = g_c[n0 + 16], w5 = g_c[n0 + 17];
    float w6 = g_c[n0 + 24], w7 = g_c[n0 + 25];

    c00 += deg0 * w0; c01 += deg0 * w1; c10 += deg0 * w2; c11 += deg0 * w3;
    c20 += deg0 * w4; c21 += deg0 * w5; c30 += deg0 * w6; c31 += deg0 * w7;
    c02 += deg1 * w0; c03 += deg1 * w1; c12 += deg1 * w2; c13 += deg1 * w3;
    c22 += deg1 * w4; c23 += deg1 * w5; c32 += deg1 * w6; c33 += deg1 * w7;

    if (LSM) {
        float m0v = fmaxf(fmaxf(fmaxf(c00, c01), fmaxf(c10, c11)),
                          fmaxf(fmaxf(c20, c21), fmaxf(c30, c31)));
        float m1v = fmaxf(fmaxf(fmaxf(c02, c03), fmaxf(c12, c13)),
                          fmaxf(fmaxf(c22, c23), fmaxf(c32, c33)));
        m0v = fmaxf(m0v, __shfl_xor_sync(0xFFFFFFFFu, m0v, 1));
        m0v = fmaxf(m0v, __shfl_xor_sync(0xFFFFFFFFu, m0v, 2));
        m1v = fmaxf(m1v, __shfl_xor_sync(0xFFFFFFFFu, m1v, 1));
        m1v = fmaxf(m1v, __shfl_xor_sync(0xFFFFFFFFu, m1v, 2));
        if (tig == 0) { sredm[row0][nq] = m0v; sredm[row1][nq] = m1v; }
        __syncthreads();
        float rm0 = fmaxf(fmaxf(sredm[row0][0], sredm[row0][1]),
                          fmaxf(sredm[row0][2], sredm[row0][3]));
        float rm1 = fmaxf(fmaxf(sredm[row1][0], sredm[row1][1]),
                          fmaxf(sredm[row1][2], sredm[row1][3]));
        float s0 = __expf(c00 - rm0) + __expf(c01 - rm0) + __expf(c10 - rm0) +
                   __expf(c11 - rm0) + __expf(c20 - rm0) + __expf(c21 - rm0) +
                   __expf(c30 - rm0) + __expf(c31 - rm0);
        float s1 = __expf(c02 - rm1) + __expf(c03 - rm1) + __expf(c12 - rm1) +
                   __expf(c13 - rm1) + __expf(c22 - rm1) + __expf(c23 - rm1) +
                   __expf(c32 - rm1) + __expf(c33 - rm1);
        s0 += __shfl_xor_sync(0xFFFFFFFFu, s0, 1);
        s0 += __shfl_xor_sync(0xFFFFFFFFu, s0, 2);
        s1 += __shfl_xor_sync(0xFFFFFFFFu, s1, 1);
        s1 += __shfl_xor_sync(0xFFFFFFFFu, s1, 2);
        if (tig == 0) { sreds[row0][nq] = s0; sreds[row1][nq] = s1; }
        __syncthreads();
        float t0 = (sreds[row0][0] + sreds[row0][1]) + (sreds[row0][2] + sreds[row0][3]);
        float t1 = (sreds[row1][0] + sreds[row1][1]) + (sreds[row1][2] + sreds[row1][3]);
        float l0 = rm0 + __logf(t0);
        float l1 = rm1 + __logf(t1);
        c00 -= l0; c01 -= l0; c10 -= l0; c11 -= l0;
        c20 -= l0; c21 -= l0; c30 -= l0; c31 -= l0;
        c02 -= l1; c03 -= l1; c12 -= l1; c13 -= l1;
        c22 -= l1; c23 -= l1; c32 -= l1; c33 -= l1;
    }

    if (FIRST) {
        if (r0 < M) {
            size_t b = ((size_t)r0 * F + n0) >> 1;
            g_hh[b]      = h2u(__floats2half2_rn(c00, c01));
            g_hh[b + 4]  = h2u(__floats2half2_rn(c10, c11));
            g_hh[b + 8]  = h2u(__floats2half2_rn(c20, c21));
            g_hh[b + 12] = h2u(__floats2half2_rn(c30, c31));
        }
        if (r1 < M) {
            size_t b = ((size_t)r1 * F + n0) >> 1;
            g_hh[b]      = h2u(__floats2half2_rn(c02, c03));
            g_hh[b + 4]  = h2u(__floats2half2_rn(c12, c13));
            g_hh[b + 8]  = h2u(__floats2half2_rn(c22, c23));
            g_hh[b + 12] = h2u(__floats2half2_rn(c32, c33));
        }
    } else {
        float* dp = dst_param;
        if (r0 < M) {
            *(float2*)&dp[(size_t)r0 * F + n0]      = make_float2(c00, c01);
            *(float2*)&dp[(size_t)r0 * F + n0 + 8]  = make_float2(c10, c11);
            *(float2*)&dp[(size_t)r0 * F + n0 + 16] = make_float2(c20, c21);
            *(float2*)&dp[(size_t)r0 * F + n0 + 24] = make_float2(c30, c31);
        }
        if (r1 < M) {
            *(float2*)&dp[(size_t)r1 * F + n0]      = make_float2(c02, c03);
            *(float2*)&dp[(size_t)r1 * F + n0 + 8]  = make_float2(c12, c13);
            *(float2*)&dp[(size_t)r1 * F + n0 + 16] = make_float2(c22, c23);
            *(float2*)&dp[(size_t)r1 * F + n0 + 24] = make_float2(c32, c33);
        }
    }
}

// ---------------- launch ----------------
extern "C" void kernel_launch(void* const* d_in, const int* in_sizes, int n_in,
                              void* d_out, int out_size) {
    const float* x  = (const float*)d_in[0];
    const void*  ei = d_in[1];
    const float* w1 = (const float*)d_in[2];
    const float* b1 = (const float*)d_in[3];
    const float* w2 = (const float*)d_in[4];
    const float* b2 = (const float*)d_in[5];
    float* out = (float*)d_out;

    int n = in_sizes[0] / F;     // 50000
    int e = in_sizes[1] / 2;     // 600000

    k_init_all<<<262, 256>>>((const unsigned int*)ei, (const float4*)x,
                             w1, w2, b1, b2, n);
    k_csr<<<CSRB, 512>>>(ei, e, n);

    int conv_blocks = (n + GBM - 1) / GBM;
    // launch 2: conv1       launch 3 (PROFILED): conv2 + log_softmax
    k_conv<true,  false><<<conv_blocks, 256>>>(nullptr, n);
    k_conv<false, true ><<<conv_blocks, 256>>>(out, n);
}

// round 17
// speedup vs baseline: 1.8654x; 1.0415x over previous
#include <cuda_runtime.h>
#include <cuda_fp16.h>
#include <stdint.h>
#include <string.h>

#define NN 50000
#define NE 600000
#define F  128
#define GBM 32
#define CSRB 98          // csr blocks (co-resident: <= SM count)

// ---------------- scratch (static device globals: no allocations) ----------
__device__ __align__(16) uint32_t g_Wf[16 * 16 * 32 * 2];// W = W1^T W2^T, tf32 B-fragment order
__device__ __align__(16) float    g_c[F];                // combined bias c = b1 W2^T + b2
__device__ int   g_cnt[NN];                              // in-degree histogram (real edges)
__device__ int   g_rowstart[NN + 1];                     // CSR row offsets (by dst)
__device__ int   g_cursor[NN];                           // fill cursors
__device__ int   g_bsum[128];                            // per-block scan sums
__device__ int   g_sorted[NE];                           // src indices sorted by dst
__device__ __align__(16) uint32_t g_xh[(size_t)NN * F / 2]; // x in fp16 (packed half2)
__device__ __align__(16) uint32_t g_hh[(size_t)NN * F / 2]; // h1 in fp16 (packed half2)
__device__ int   d_is64;                                 // 1 if edge_index is int64
__device__ int   g_bar1, g_bar2, g_bar3;                 // csr spin barriers

__device__ __forceinline__ uint32_t f2tf(float f) {
    uint32_t u;
    asm("cvt.rna.tf32.f32 %0, %1;" : "=r"(u) : "f"(f));
    return u;
}

__device__ __forceinline__ uint32_t h2u(__half2 h) {
    uint32_t u;
    memcpy(&u, &h, 4);
    return u;
}

__device__ __forceinline__ __half2 u2h(uint32_t u) {
    __half2 h;
    memcpy(&h, &u, 4);
    return h;
}

// 32-bit index load: for int64 (little-endian, values < 2^31) read the low word.
__device__ __forceinline__ int load_idx(const void* ei, int e, int row, int i) {
    const int* p = (const int*)ei;
    if (d_is64) return p[2 * ((size_t)row * e + i)];
    return p[row * e + i];
}

// ---------------- launch 0: detect + zero + x->fp16 + weight fold -----------
__global__ __launch_bounds__(256) void k_init_all(
    const unsigned int* __restrict__ w, const float4* __restrict__ x4,
    const float* __restrict__ w1, const float* __restrict__ w2,
    const float* __restrict__ b1, const float* __restrict__ b2, int n) {
    int b = blockIdx.x, t = threadIdx.x;
    if (b == 0) {
        __shared__ int nz;
        if (t == 0) { nz = 0; g_bar1 = 0; g_bar2 = 0; g_bar3 = 0; }
        __syncthreads();
        int local = 0;
        for (int i = t; i < 2048; i += blockDim.x)
            if (w[2 * i + 1] != 0u) local = 1;
        if (local) atomicOr(&nz, 1);
        __syncthreads();
        if (t == 0) d_is64 = (nz == 0) ? 1 : 0;
        return;
    }
    if (b <= 196) {
        int i = (b - 1) * 256 + t;
        if (i < n) g_cnt[i] = 0;
        int total = n * (F / 8);
        int stride = 196 * 256;
        for (int idx = i; idx < total; idx += stride) {
            float4 v0 = x4[idx * 2];
            float4 v1 = x4[idx * 2 + 1];
            uint4 o;
            o.x = h2u(__floats2half2_rn(v0.x, v0.y));
            o.y = h2u(__floats2half2_rn(v0.z, v0.w));
            o.z = h2u(__floats2half2_rn(v1.x, v1.y));
            o.w = h2u(__floats2half2_rn(v1.z, v1.w));
            ((uint4*)g_xh)[idx] = o;
        }
        return;
    }
    int k = (b - 197) * 2 + (t >> 7);
    int i = t & 127;
    if (k > F) return;
    if (k == F) {
        float s = b2[i];
#pragma unroll 4
        for (int j = 0; j < F; j++) s += b1[j] * w2[i * F + j];
        g_c[i] = s;
        return;
    }
    float s = 0.f;
#pragma unroll 4
    for (int j = 0; j < F; j++) s += w1[j * F + k] * w2[i * F + j];
    int idx = ((k >> 3) * 512 + (i >> 3) * 32 + (i & 7) * 4 + (k & 3)) * 2 + ((k >> 2) & 1);
    g_Wf[idx] = f2tf(s);
}

// ---------------- launch 1: fused CSR (hist -> scan -> offsets -> fill) -----
__device__ __forceinline__ void grid_bar(int* ctr, int nb) {
    __syncthreads();
    if (threadIdx.x == 0) {
        __threadfence();
        atomicAdd(ctr, 1);
        while (atomicAdd(ctr, 0) < nb) { }
    }
    __syncthreads();
}

__global__ __launch_bounds__(512) void k_csr(const void* __restrict__ ei, int e, int n) {
    __shared__ int wsum[16];
    __shared__ int off_s;
    int t = threadIdx.x, b = blockIdx.x;
    int nb = gridDim.x;
    int nt = nb * 512;
    int lane = t & 31, w = t >> 5;

    for (int i = b * 512 + t; i < e; i += nt) {
        int dst = load_idx(ei, e, 1, i);
        if ((unsigned)dst < (unsigned)n) atomicAdd(&g_cnt[dst], 1);
    }
    grid_bar(&g_bar1, nb);

    int gidx = b * 512 + t;
    int v = (gidx < n) ? g_cnt[gidx] : 0;
    int x = v;
#pragma unroll
    for (int o = 1; o < 32; o <<= 1) {
        int y = __shfl_up_sync(0xFFFFFFFFu, x, o);
        if (lane >= o) x += y;
    }
    if (lane == 31) wsum[w] = x;
    __syncthreads();
    if (w == 0 && lane < 16) {
        int s = wsum[lane];
#pragma unroll
        for (int o = 1; o < 16; o <<= 1) {
            int y = __shfl_up_sync(0xFFFFu, s, o);
            if (lane >= o) s += y;
        }
        wsum[lane] = s;
    }
    __syncthreads();
    int incl = x + (w > 0 ? wsum[w - 1] : 0);
    if (gidx < n) g_rowstart[gidx] = incl - v;
    if (t == 511) g_bsum[b] = incl;
    grid_bar(&g_bar2, nb);

    if (t < 32) {
        int acc = 0, tot = 0;
        for (int j = t; j < nb; j += 32) {
            int vv = g_bsum[j];
            tot += vv;
            if (j < b) acc += vv;
        }
#pragma unroll
        for (int o = 16; o; o >>= 1) {
            acc += __shfl_xor_sync(0xFFFFFFFFu, acc, o);
            tot += __shfl_xor_sync(0xFFFFFFFFu, tot, o);
        }
        if (t == 0) {
            off_s = acc;
            if (b == 0) g_rowstart[n] = tot;
        }
    }
    __syncthreads();
    if (gidx < n) {
        int vv = g_rowstart[gidx] + off_s;
        g_rowstart[gidx] = vv;
        g_cursor[gidx]   = vv;
    }
    grid_bar(&g_bar3, nb);

    for (int i = b * 512 + t; i < e; i += nt) {
        int src = load_idx(ei, e, 0, i);
        int dst = load_idx(ei, e, 1, i);
        if ((unsigned)src < (unsigned)n && (unsigned)dst < (unsigned)n) {
            int p = atomicAdd(&g_cursor[dst], 1);
            g_sorted[p] = src;
        }
    }
}

// ---------------- fused conv: 16B 2-edge gather + TF32 MMA + epilogue -------
// GBM=32 rows/block, 256 threads / 8 warps. Gather: 16 lanes cover a 256B row
// (uint4/lane); half-warp 0 gathers edge i, half-warp 1 edge i+1 -> one warp
// load instruction = 2 edges (LDG count halved vs uint2). Row accumulators:
// 8 fp32/lane (features sl*8..sl*8+7); half-warps merged via shfl_xor(16).
#define MMA_TF32(c0, c1, c2, c3, bx, by)                                      \
    asm volatile(                                                             \
        "mma.sync.aligned.m16n8k8.row.col.f32.tf32.tf32.f32 "                 \
        "{%0,%1,%2,%3}, {%4,%5,%6,%7}, {%8,%9}, {%0,%1,%2,%3};"               \
        : "+f"(c0), "+f"(c1), "+f"(c2), "+f"(c3)                              \
        : "r"(a0), "r"(a1), "r"(a2), "r"(a3), "r"(bx), "r"(by))

#define ACC_U4_F32(u)                                                         \
    do {                                                                      \
        float2 q;                                                             \
        q = __half22float2(u2h((u).x)); a0 += q.x; a1 += q.y;                 \
        q = __half22float2(u2h((u).y)); a2 += q.x; a3 += q.y;                 \
        q = __half22float2(u2h((u).z)); a4 += q.x; a5 += q.y;                 \
        q = __half22float2(u2h((u).w)); a6 += q.x; a7 += q.y;                 \
    } while (0)

template <bool FIRST, bool LSM>
__global__ __launch_bounds__(256) void k_conv(float* __restrict__ dst_param, int M) {
    __shared__ uint32_t As[GBM * 132];
    __shared__ float sredm[GBM][4];
    __shared__ float sreds[GBM][4];
    int tid = threadIdx.x;
    int warp = tid >> 5, lane = tid & 31;
    int gid = lane >> 2, tig = lane & 3;
    int half = lane >> 4;        // 0: even edge, 1: odd edge
    int sl   = lane & 15;        // 16B chunk within row
    int m0 = blockIdx.x * GBM;

    const uint4* hv4 = FIRST ? (const uint4*)g_xh : (const uint4*)g_hh;

    // ---- aggregation: warp handles rows [warp*4, warp*4+4)
#pragma unroll
    for (int r = 0; r < 4; r++) {
        int row = warp * 4 + r;
        int gm  = m0 + row;
        float a0 = 0.f, a1 = 0.f, a2 = 0.f, a3 = 0.f;
        float a4 = 0.f, a5 = 0.f, a6 = 0.f, a7 = 0.f;
        if (gm < M) {
            if (half == 0) {                     // self loop (counted once)
                uint4 u = hv4[(size_t)gm * 16 + sl];
                ACC_U4_F32(u);
            }
            int s = g_rowstart[gm], e2 = g_rowstart[gm + 1];
            int i = s;
            for (; i + 7 < e2; i += 8) {         // 8 edges: 4 loads/lane, fp16 tree of 4
                int j0 = g_sorted[i     + half];
                int j1 = g_sorted[i + 2 + half];
                int j2 = g_sorted[i + 4 + half];
                int j3 = g_sorted[i + 6 + half];
                uint4 u0 = hv4[(size_t)j0 * 16 + sl];
                uint4 u1 = hv4[(size_t)j1 * 16 + sl];
                uint4 u2 = hv4[(size_t)j2 * 16 + sl];
                uint4 u3 = hv4[(size_t)j3 * 16 + sl];
                __half2 hx = __hadd2(__hadd2(u2h(u0.x), u2h(u1.x)),
                                     __hadd2(u2h(u2.x), u2h(u3.x)));
                __half2 hy = __hadd2(__hadd2(u2h(u0.y), u2h(u1.y)),
                                     __hadd2(u2h(u2.y), u2h(u3.y)));
                __half2 hz = __hadd2(__hadd2(u2h(u0.z), u2h(u1.z)),
                                     __hadd2(u2h(u2.z), u2h(u3.z)));
                __half2 hw = __hadd2(__hadd2(u2h(u0.w), u2h(u1.w)),
                                     __hadd2(u2h(u2.w), u2h(u3.w)));
                float2 q;
                q = __half22float2(hx); a0 += q.x; a1 += q.y;
                q = __half22float2(hy); a2 += q.x; a3 += q.y;
                q = __half22float2(hz); a4 += q.x; a5 += q.y;
                q = __half22float2(hw); a6 += q.x; a7 += q.y;
            }
            for (; i + 1 < e2; i += 2) {         // 2 edges, fp32 adds
                int j = g_sorted[i + half];
                uint4 u = hv4[(size_t)j * 16 + sl];
                ACC_U4_F32(u);
            }
            if (i < e2 && half == 0) {           // single tail edge
                int j = g_sorted[i];
                uint4 u = hv4[(size_t)j * 16 + sl];
                ACC_U4_F32(u);
            }
        }
        // merge half-warps (edge-parity partials)
        a0 += __shfl_xor_sync(0xFFFFFFFFu, a0, 16);
        a1 += __shfl_xor_sync(0xFFFFFFFFu, a1, 16);
        a2 += __shfl_xor_sync(0xFFFFFFFFu, a2, 16);
        a3 += __shfl_xor_sync(0xFFFFFFFFu, a3, 16);
        a4 += __shfl_xor_sync(0xFFFFFFFFu, a4, 16);
        a5 += __shfl_xor_sync(0xFFFFFFFFu, a5, 16);
        a6 += __shfl_xor_sync(0xFFFFFFFFu, a6, 16);
        a7 += __shfl_xor_sync(0xFFFFFFFFu, a7, 16);
        if (half == 0) {
            uint4 t0, t1;
            t0.x = f2tf(a0); t0.y = f2tf(a1); t0.z = f2tf(a2); t0.w = f2tf(a3);
            t1.x = f2tf(a4); t1.y = f2tf(a5); t1.z = f2tf(a6); t1.w = f2tf(a7);
            *(uint4*)&As[row * 132 + sl * 8]     = t0;
            *(uint4*)&As[row * 132 + sl * 8 + 4] = t1;
        }
    }
    __syncthreads();

    int mrow0 = (warp & 1) * 16;
    int nq    = warp >> 1;
    int nt0   = nq * 4;

    float c00 = 0.f, c01 = 0.f, c02 = 0.f, c03 = 0.f;
    float c10 = 0.f, c11 = 0.f, c12 = 0.f, c13 = 0.f;
    float c20 = 0.f, c21 = 0.f, c22 = 0.f, c23 = 0.f;
    float c30 = 0.f, c31 = 0.f, c32 = 0.f, c33 = 0.f;

    int abase = (mrow0 + gid) * 132;
    for (int kc = 0; kc < 16; kc++) {
        uint32_t a0 = As[abase + kc * 8 + tig];
        uint32_t a1 = As[abase + 8 * 132 + kc * 8 + tig];
        uint32_t a2 = As[abase + kc * 8 + tig + 4];
        uint32_t a3 = As[abase + 8 * 132 + kc * 8 + tig + 4];
        const uint2* wf = (const uint2*)g_Wf + (size_t)kc * 512 + nt0 * 32 + lane;
        uint2 b0 = wf[0];
        uint2 b1 = wf[32];
        uint2 b2 = wf[64];
        uint2 b3 = wf[96];
        MMA_TF32(c00, c01, c02, c03, b0.x, b0.y);
        MMA_TF32(c10, c11, c12, c13, b1.x, b1.y);
        MMA_TF32(c20, c21, c22, c23, b2.x, b2.y);
        MMA_TF32(c30, c31, c32, c33, b3.x, b3.y);
    }

    int row0 = mrow0 + gid;
    int row1 = row0 + 8;
    int r0 = m0 + row0;
    int r1 = m0 + row1;
    float deg0 = (r0 < M) ? (float)(g_cnt[r0] + 1) : 0.f;
    float deg1 = (r1 < M) ? (float)(g_cnt[r1] + 1) : 0.f;
    int n0 = nt0 * 8 + 2 * tig;

    float w0 = g_c[n0],      w1 = g_c[n0 + 1];
    float w2 = g_c[n0 + 8],  w3 = g_c[n0 + 9];
    float w4 = g_c[n0 + 16], w5 = g_c[n0 + 17];
    float w6 = g_c[n0 + 24], w7 = g_c[n0 + 25];

    c00 += deg0 * w0; c01 += deg0 * w1; c10 += deg0 * w2; c11 += deg0 * w3;
    c20 += deg0 * w4; c21 += deg0 * w5; c30 += deg0 * w6; c31 += deg0 * w7;
    c02 += deg1 * w0; c03 += deg1 * w1; c12 += deg1 * w2; c13 += deg1 * w3;
    c22 += deg1 * w4; c23 += deg1 * w5; c32 += deg1 * w6; c33 += deg1 * w7;

    if (LSM) {
        float m0v = fmaxf(fmaxf(fmaxf(c00, c01), fmaxf(c10, c11)),
                          fmaxf(fmaxf(c20, c21), fmaxf(c30, c31)));
        float m1v = fmaxf(fmaxf(fmaxf(c02, c03), fmaxf(c12, c13)),
                          fmaxf(fmaxf(c22, c23), fmaxf(c32, c33)));
        m0v = fmaxf(m0v, __shfl_xor_sync(0xFFFFFFFFu, m0v, 1));
        m0v = fmaxf(m0v, __shfl_xor_sync(0xFFFFFFFFu, m0v, 2));
        m1v = fmaxf(m1v, __shfl_xor_sync(0xFFFFFFFFu, m1v, 1));
        m1v = fmaxf(m1v, __shfl_xor_sync(0xFFFFFFFFu, m1v, 2));
        if (tig == 0) { sredm[row0][nq] = m0v; sredm[row1][nq] = m1v; }
        __syncthreads();
        float rm0 = fmaxf(fmaxf(sredm[row0][0], sredm[row0][1]),
                          fmaxf(sredm[row0][2], sredm[row0][3]));
        float rm1 = fmaxf(fmaxf(sredm[row1][0], sredm[row1][1]),
                          fmaxf(sredm[row1][2], sredm[row1][3]));
        float s0 = __expf(c00 - rm0) + __expf(c01 - rm0) + __expf(c10 - rm0) +
                   __expf(c11 - rm0) + __expf(c20 - rm0) + __expf(c21 - rm0) +
                   __expf(c30 - rm0) + __expf(c31 - rm0);
        float s1 = __expf(c02 - rm1) + __expf(c03 - rm1) + __expf(c12 - rm1) +
                   __expf(c13 - rm1) + __expf(c22 - rm1) + __expf(c23 - rm1) +
                   __expf(c32 - rm1) + __expf(c33 - rm1);
        s0 += __shfl_xor_sync(0xFFFFFFFFu, s0, 1);
        s0 += __shfl_xor_sync(0xFFFFFFFFu, s0, 2);
        s1 += __shfl_xor_sync(0xFFFFFFFFu, s1, 1);
        s1 += __shfl_xor_sync(0xFFFFFFFFu, s1, 2);
        if (tig == 0) { sreds[row0][nq] = s0; sreds[row1][nq] = s1; }
        __syncthreads();
        float t0 = (sreds[row0][0] + sreds[row0][1]) + (sreds[row0][2] + sreds[row0][3]);
        float t1 = (sreds[row1][0] + sreds[row1][1]) + (sreds[row1][2] + sreds[row1][3]);
        float l0 = rm0 + __logf(t0);
        float l1 = rm1 + __logf(t1);
        c00 -= l0; c01 -= l0; c10 -= l0; c11 -= l0;
        c20 -= l0; c21 -= l0; c30 -= l0; c31 -= l0;
        c02 -= l1; c03 -= l1; c12 -= l1; c13 -= l1;
        c22 -= l1; c23 -= l1; c32 -= l1; c33 -= l1;
    }

    if (FIRST) {
        if (r0 < M) {
            size_t b = ((size_t)r0 * F + n0) >> 1;
            g_hh[b]      = h2u(__floats2half2_rn(c00, c01));
            g_hh[b + 4]  = h2u(__floats2half2_rn(c10, c11));
            g_hh[b + 8]  = h2u(__floats2half2_rn(c20, c21));
            g_hh[b + 12] = h2u(__floats2half2_rn(c30, c31));
        }
        if (r1 < M) {
            size_t b = ((size_t)r1 * F + n0) >> 1;
            g_hh[b]      = h2u(__floats2half2_rn(c02, c03));
            g_hh[b + 4]  = h2u(__floats2half2_rn(c12, c13));
            g_hh[b + 8]  = h2u(__floats2half2_rn(c22, c23));
            g_hh[b + 12] = h2u(__floats2half2_rn(c32, c33));
        }
    } else {
        float* dp = dst_param;
        if (r0 < M) {
            *(float2*)&dp[(size_t)r0 * F + n0]      = make_float2(c00, c01);
            *(float2*)&dp[(size_t)r0 * F + n0 + 8]  = make_float2(c10, c11);
            *(float2*)&dp[(size_t)r0 * F + n0 + 16] = make_float2(c20, c21);
            *(float2*)&dp[(size_t)r0 * F + n0 + 24] = make_float2(c30, c31);
        }
        if (r1 < M) {
            *(float2*)&dp[(size_t)r1 * F + n0]      = make_float2(c02, c03);
            *(float2*)&dp[(size_t)r1 * F + n0 + 8]  = make_float2(c12, c13);
            *(float2*)&dp[(size_t)r1 * F + n0 + 16] = make_float2(c22, c23);
            *(float2*)&dp[(size_t)r1 * F + n0 + 24] = make_float2(c32, c33);
        }
    }
}

// ---------------- launch ----------------
extern "C" void kernel_launch(void* const* d_in, const int* in_sizes, int n_in,
                              void* d_out, int out_size) {
    const float* x  = (const float*)d_in[0];
    const void*  ei = d_in[1];
    const float* w1 = (const float*)d_in[2];
    const float* b1 = (const float*)d_in[3];
    const float* w2 = (const float*)d_in[4];
    const float* b2 = (const float*)d_in[5];
    float* out = (float*)d_out;

    int n = in_sizes[0] / F;     // 50000
    int e = in_sizes[1] / 2;     // 600000

    k_init_all<<<262, 256>>>((const unsigned int*)ei, (const float4*)x,
                             w1, w2, b1, b2, n);
    k_csr<<<CSRB, 512>>>(ei, e, n);

    int conv_blocks = (n + GBM - 1) / GBM;
    // launch 2: conv1       launch 3 (PROFILED): conv2 + log_softmax
    k_conv<true,  false><<<conv_blocks, 256>>>(nullptr, n);
    k_conv<false, true ><<<conv_blocks, 256>>>(out, n);
}